// round 2
// baseline (speedup 1.0000x reference)
#include <cuda_runtime.h>
#include <math.h>

#define NHEADS 16
#define HEAD   64
#define HD     (NHEADS * HEAD)   /* 1024 floats per token row */
#define BSZ    64
#define NBLK   64
#define SMEM_BYTES (4 * 64 * 64 * 4)   /* sQ sK sV sP = 64 KiB */

// One CTA = (q-block, head). 128 threads = 4 warps.
// Thread (ty = tid>>3 in 0..15, tx = tid&7 in 0..7) owns a 4-row x 8-col register
// tile: rows ty*4..+3, cols/dims {tx*4..+3} U {32+tx*4..+3}.
// sQ/sK/sP are stored with a 16B-granular XOR swizzle: 16B-group g of row r lives
// at slot (g ^ (r>>2)). This makes every GEMM-phase LDS.128 bank-conflict-free.
__global__ __launch_bounds__(128)
void bs_attn_kernel(const float* __restrict__ qg_,
                    const float* __restrict__ kg_,
                    const float* __restrict__ vg_,
                    float* __restrict__ out)
{
    const int qi = (NBLK - 1) - (int)blockIdx.x;   // heavy blocks first
    const int h  = (int)blockIdx.y;

    extern __shared__ float sm[];
    float* sQ = sm;            // 64x64 swizzled
    float* sK = sm + 4096;     // 64x64 swizzled
    float* sV = sm + 8192;     // 64x64 natural
    float* sP = sm + 12288;    // 64x64 swizzled

    const int tid = (int)threadIdx.x;
    const int ty  = tid >> 3;
    const int tx  = tid & 7;
    const int r0  = ty << 2;

    // ---- load Q tile (coalesced float4, swizzled store) ----
    {
        const float* qg = qg_ + (size_t)(qi * BSZ) * HD + h * HEAD;
        #pragma unroll
        for (int e = 0; e < 8; ++e) {
            int idx = (e << 7) + tid;          // 0..1023
            int row = idx >> 4, d4 = idx & 15;
            float4 val = *reinterpret_cast<const float4*>(qg + row * HD + (d4 << 2));
            int slot = d4 ^ (row >> 2);
            *reinterpret_cast<float4*>(sQ + (row << 6) + (slot << 2)) = val;
        }
    }

    // ---- enumerate k-blocks: verticals (j ≡ 7-h mod 8, j <= qi-8), then locals ----
    const int rv = (7 - (h & 7)) & 7;
    const int nv = (qi - 8 >= rv) ? (((qi - 8 - rv) >> 3) + 1) : 0;
    const int j0 = (qi - 7 > 0) ? (qi - 7) : 0;
    const int nb = nv + (qi - j0 + 1);

    float m_i[4], l_i[4], o[4][8];
    #pragma unroll
    for (int rr = 0; rr < 4; ++rr) {
        m_i[rr] = -INFINITY; l_i[rr] = 0.0f;
        #pragma unroll
        for (int b = 0; b < 8; ++b) o[rr][b] = 0.0f;
    }
    const float sc = 0.125f;   // 1/sqrt(64)

    for (int it = 0; it < nb; ++it) {
        const int kb = (it < nv) ? (rv + (it << 3)) : (j0 + it - nv);

        __syncthreads();   // previous iteration's GEMM2 reads of sP/sV complete
        // ---- load K (swizzled) and V (natural) tiles ----
        {
            const float* kg = kg_ + (size_t)(kb * BSZ) * HD + h * HEAD;
            const float* vg = vg_ + (size_t)(kb * BSZ) * HD + h * HEAD;
            #pragma unroll
            for (int e = 0; e < 8; ++e) {
                int idx = (e << 7) + tid;
                int row = idx >> 4, d4 = idx & 15;
                float4 k4 = *reinterpret_cast<const float4*>(kg + row * HD + (d4 << 2));
                int slot = d4 ^ (row >> 2);
                *reinterpret_cast<float4*>(sK + (row << 6) + (slot << 2)) = k4;
                float4 v4 = *reinterpret_cast<const float4*>(vg + row * HD + (d4 << 2));
                *reinterpret_cast<float4*>(sV + (row << 6) + (d4 << 2)) = v4;
            }
        }
        __syncthreads();

        // ---- GEMM1: S[4][8] = Q * K^T (this thread's tile) ----
        float S[4][8];
        #pragma unroll
        for (int rr = 0; rr < 4; ++rr)
            #pragma unroll
            for (int b = 0; b < 8; ++b) S[rr][b] = 0.0f;

        #pragma unroll
        for (int d4 = 0; d4 < 16; ++d4) {
            float4 qf[4];
            #pragma unroll
            for (int rr = 0; rr < 4; ++rr)   // (r0+rr)>>2 == ty
                qf[rr] = *reinterpret_cast<const float4*>(
                    sQ + ((r0 + rr) << 6) + ((d4 ^ ty) << 2));
            float4 kf[8];
            #pragma unroll
            for (int cc = 0; cc < 4; ++cc) {
                kf[cc]     = *reinterpret_cast<const float4*>(
                    sK + (((tx << 2) + cc) << 6)      + ((d4 ^ tx) << 2));
                kf[4 + cc] = *reinterpret_cast<const float4*>(
                    sK + ((32 + (tx << 2) + cc) << 6) + ((d4 ^ (8 | tx)) << 2));
            }
            #pragma unroll
            for (int rr = 0; rr < 4; ++rr)
                #pragma unroll
                for (int b = 0; b < 8; ++b) {
                    S[rr][b] = fmaf(qf[rr].x, kf[b].x, S[rr][b]);
                    S[rr][b] = fmaf(qf[rr].y, kf[b].y, S[rr][b]);
                    S[rr][b] = fmaf(qf[rr].z, kf[b].z, S[rr][b]);
                    S[rr][b] = fmaf(qf[rr].w, kf[b].w, S[rr][b]);
                }
        }

        // ---- causal mask inside the diagonal block ----
        if (kb == qi) {
            #pragma unroll
            for (int rr = 0; rr < 4; ++rr) {
                int row = r0 + rr;
                #pragma unroll
                for (int cc = 0; cc < 4; ++cc) {
                    if ((tx << 2) + cc > row)      S[rr][cc]     = -INFINITY;
                    if (32 + (tx << 2) + cc > row) S[rr][4 + cc] = -INFINITY;
                }
            }
        }

        // ---- online softmax (row reduction across the 8 tx lanes) ----
        #pragma unroll
        for (int rr = 0; rr < 4; ++rr) {
            float mx = S[rr][0];
            #pragma unroll
            for (int b = 1; b < 8; ++b) mx = fmaxf(mx, S[rr][b]);
            mx = fmaxf(mx, __shfl_xor_sync(0xffffffffu, mx, 1));
            mx = fmaxf(mx, __shfl_xor_sync(0xffffffffu, mx, 2));
            mx = fmaxf(mx, __shfl_xor_sync(0xffffffffu, mx, 4));
            mx *= sc;
            float mnew = fmaxf(m_i[rr], mx);
            float fac  = __expf(m_i[rr] - mnew);   // 0 on first block (m_i = -inf)
            m_i[rr] = mnew;
            float ls = 0.0f;
            #pragma unroll
            for (int b = 0; b < 8; ++b) {
                float p = __expf(fmaf(S[rr][b], sc, -mnew));
                S[rr][b] = p;
                ls += p;
            }
            l_i[rr] = fmaf(l_i[rr], fac, ls);      // per-thread partial row sum
            #pragma unroll
            for (int b = 0; b < 8; ++b) o[rr][b] *= fac;
        }

        // ---- write P tile (swizzled) ----
        {
            const int sA = ((tx ^ ty) << 2);        // col group tx*4..+3
            const int sB = (((8 | tx) ^ ty) << 2);  // col group 32+tx*4..+3
            #pragma unroll
            for (int rr = 0; rr < 4; ++rr) {
                *reinterpret_cast<float4*>(sP + ((r0 + rr) << 6) + sA) =
                    make_float4(S[rr][0], S[rr][1], S[rr][2], S[rr][3]);
                *reinterpret_cast<float4*>(sP + ((r0 + rr) << 6) + sB) =
                    make_float4(S[rr][4], S[rr][5], S[rr][6], S[rr][7]);
            }
        }
        __syncthreads();

        // ---- GEMM2: O += P * V ----
        #pragma unroll
        for (int j4 = 0; j4 < 16; ++j4) {
            float pf[4][4];
            #pragma unroll
            for (int rr = 0; rr < 4; ++rr) {
                float4 t = *reinterpret_cast<const float4*>(
                    sP + ((r0 + rr) << 6) + ((j4 ^ ty) << 2));
                pf[rr][0] = t.x; pf[rr][1] = t.y; pf[rr][2] = t.z; pf[rr][3] = t.w;
            }
            #pragma unroll
            for (int jj = 0; jj < 4; ++jj) {
                int j = (j4 << 2) + jj;
                float4 va = *reinterpret_cast<const float4*>(sV + (j << 6) + (tx << 2));
                float4 vb = *reinterpret_cast<const float4*>(sV + (j << 6) + 32 + (tx << 2));
                #pragma unroll
                for (int rr = 0; rr < 4; ++rr) {
                    float p = pf[rr][jj];
                    o[rr][0] = fmaf(p, va.x, o[rr][0]);
                    o[rr][1] = fmaf(p, va.y, o[rr][1]);
                    o[rr][2] = fmaf(p, va.z, o[rr][2]);
                    o[rr][3] = fmaf(p, va.w, o[rr][3]);
                    o[rr][4] = fmaf(p, vb.x, o[rr][4]);
                    o[rr][5] = fmaf(p, vb.y, o[rr][5]);
                    o[rr][6] = fmaf(p, vb.z, o[rr][6]);
                    o[rr][7] = fmaf(p, vb.w, o[rr][7]);
                }
            }
        }
    }

    // ---- finalize: reduce l across tx, divide, store [T,H,D] ----
    #pragma unroll
    for (int rr = 0; rr < 4; ++rr) {
        float l = l_i[rr];
        l += __shfl_xor_sync(0xffffffffu, l, 1);
        l += __shfl_xor_sync(0xffffffffu, l, 2);
        l += __shfl_xor_sync(0xffffffffu, l, 4);
        float inv = 1.0f / l;
        float* og = out + (size_t)(qi * BSZ + r0 + rr) * HD + h * HEAD;
        float4 oa = make_float4(o[rr][0] * inv, o[rr][1] * inv, o[rr][2] * inv, o[rr][3] * inv);
        float4 ob = make_float4(o[rr][4] * inv, o[rr][5] * inv, o[rr][6] * inv, o[rr][7] * inv);
        *reinterpret_cast<float4*>(og + (tx << 2)) = oa;
        *reinterpret_cast<float4*>(og + 32 + (tx << 2)) = ob;
    }
}

extern "C" void kernel_launch(void* const* d_in, const int* in_sizes, int n_in,
                              void* d_out, int out_size)
{
    const float* q = (const float*)d_in[0];
    const float* k = (const float*)d_in[1];
    const float* v = (const float*)d_in[2];
    // d_in[3] = cu_seqlens_k, fixed [0, 4096] for this problem — unused.
    float* out = (float*)d_out;

    cudaFuncSetAttribute(bs_attn_kernel,
                         cudaFuncAttributeMaxDynamicSharedMemorySize, SMEM_BYTES);
    dim3 grid(NBLK, NHEADS);
    bs_attn_kernel<<<grid, 128, SMEM_BYTES>>>(q, k, v, out);
}

// round 4
// speedup vs baseline: 1.1246x; 1.1246x over previous
#include <cuda_runtime.h>
#include <math.h>

#define NHEADS 16
#define HEAD   64
#define HD     (NHEADS * HEAD)   /* 1024 floats per token row */
#define BSZ    64
#define NBLK   64
#define SMEM_BYTES (4 * 64 * 64 * 4)   /* sQ sK sV sP = 64 KiB */

// Packed f32x2 helpers (SASS FFMA2 path — ptxas never emits these from C++).
__device__ __forceinline__ void ffma2(unsigned long long& d,
                                      unsigned long long a,
                                      unsigned long long b) {
    asm("fma.rn.f32x2 %0, %1, %2, %0;" : "+l"(d) : "l"(a), "l"(b));
}
__device__ __forceinline__ unsigned long long pack2(float x) {
    unsigned long long r;
    asm("mov.b64 %0, {%1, %1};" : "=l"(r) : "f"(x));
    return r;
}
__device__ __forceinline__ void mul2(unsigned long long& d, unsigned long long a) {
    asm("mul.rn.f32x2 %0, %0, %1;" : "+l"(d) : "l"(a));
}
__device__ __forceinline__ float2 unpack2(unsigned long long a) {
    float2 r;
    asm("mov.b64 {%0, %1}, %2;" : "=f"(r.x), "=f"(r.y) : "l"(a));
    return r;
}

union F4 {            // view a float4 register quad as two 64-bit f32x2 operands
    float4 f;
    unsigned long long u[2];
};

// One CTA = (q-block, head). 128 threads = 4 warps.
// Thread (ty = tid>>3, tx = tid&7) owns rows ty*4..+3, cols {tx*4..+3} U {32+tx*4..+3}.
// sQ/sK/sP use a 16B-granular XOR swizzle: group g of row r lives at slot (g ^ (r>>2)),
// making every GEMM-phase LDS.128 bank-conflict-free.
__global__ __launch_bounds__(128)
void bs_attn_kernel(const float* __restrict__ qg_,
                    const float* __restrict__ kg_,
                    const float* __restrict__ vg_,
                    float* __restrict__ out)
{
    const int qi = (NBLK - 1) - (int)blockIdx.x;   // heavy blocks first
    const int h  = (int)blockIdx.y;

    extern __shared__ float sm[];
    float* sQ = sm;            // 64x64 swizzled
    float* sK = sm + 4096;     // 64x64 swizzled
    float* sV = sm + 8192;     // 64x64 natural
    float* sP = sm + 12288;    // 64x64 swizzled

    const int tid = (int)threadIdx.x;
    const int ty  = tid >> 3;
    const int tx  = tid & 7;
    const int r0  = ty << 2;

    // ---- load Q tile (coalesced float4, swizzled store) ----
    {
        const float* qg = qg_ + (size_t)(qi * BSZ) * HD + h * HEAD;
        #pragma unroll
        for (int e = 0; e < 8; ++e) {
            int idx = (e << 7) + tid;          // 0..1023
            int row = idx >> 4, d4 = idx & 15;
            float4 val = *reinterpret_cast<const float4*>(qg + row * HD + (d4 << 2));
            int slot = d4 ^ (row >> 2);
            *reinterpret_cast<float4*>(sQ + (row << 6) + (slot << 2)) = val;
        }
    }

    // ---- enumerate k-blocks: verticals (j ≡ 7-h mod 8, j <= qi-8), then locals ----
    const int rv = (7 - (h & 7)) & 7;
    const int nv = (qi - 8 >= rv) ? (((qi - 8 - rv) >> 3) + 1) : 0;
    const int j0 = (qi - 7 > 0) ? (qi - 7) : 0;
    const int nb = nv + (qi - j0 + 1);

    float m_i[4], l_i[4];
    unsigned long long Op[4][4];   // packed output accumulators (col pairs)
    #pragma unroll
    for (int rr = 0; rr < 4; ++rr) {
        m_i[rr] = -INFINITY; l_i[rr] = 0.0f;
        #pragma unroll
        for (int c = 0; c < 4; ++c) Op[rr][c] = 0ull;
    }
    const float sc = 0.125f;   // 1/sqrt(64)

    for (int it = 0; it < nb; ++it) {
        const int kb = (it < nv) ? (rv + (it << 3)) : (j0 + it - nv);

        __syncthreads();   // previous iteration's GEMM2 reads of sP/sV complete
        // ---- load K (swizzled) and V (natural) tiles ----
        {
            const float* kg = kg_ + (size_t)(kb * BSZ) * HD + h * HEAD;
            const float* vg = vg_ + (size_t)(kb * BSZ) * HD + h * HEAD;
            #pragma unroll
            for (int e = 0; e < 8; ++e) {
                int idx = (e << 7) + tid;
                int row = idx >> 4, d4 = idx & 15;
                float4 k4 = *reinterpret_cast<const float4*>(kg + row * HD + (d4 << 2));
                int slot = d4 ^ (row >> 2);
                *reinterpret_cast<float4*>(sK + (row << 6) + (slot << 2)) = k4;
                float4 v4 = *reinterpret_cast<const float4*>(vg + row * HD + (d4 << 2));
                *reinterpret_cast<float4*>(sV + (row << 6) + (d4 << 2)) = v4;
            }
        }
        __syncthreads();

        // ---- GEMM1: Sp[4][8] = Q * K^T, packed over dim-parity ----
        unsigned long long Sp[4][8];
        #pragma unroll
        for (int rr = 0; rr < 4; ++rr)
            #pragma unroll
            for (int b = 0; b < 8; ++b) Sp[rr][b] = 0ull;

        #pragma unroll
        for (int d4 = 0; d4 < 16; ++d4) {
            F4 qf[4];
            #pragma unroll
            for (int rr = 0; rr < 4; ++rr)   // (r0+rr)>>2 == ty
                qf[rr].f = *reinterpret_cast<const float4*>(
                    sQ + ((r0 + rr) << 6) + ((d4 ^ ty) << 2));
            F4 kf[8];
            #pragma unroll
            for (int cc = 0; cc < 4; ++cc) {
                kf[cc].f     = *reinterpret_cast<const float4*>(
                    sK + (((tx << 2) + cc) << 6)      + ((d4 ^ tx) << 2));
                kf[4 + cc].f = *reinterpret_cast<const float4*>(
                    sK + ((32 + (tx << 2) + cc) << 6) + ((d4 ^ (8 | tx)) << 2));
            }
            #pragma unroll
            for (int rr = 0; rr < 4; ++rr)
                #pragma unroll
                for (int b = 0; b < 8; ++b) {
                    ffma2(Sp[rr][b], qf[rr].u[0], kf[b].u[0]);
                    ffma2(Sp[rr][b], qf[rr].u[1], kf[b].u[1]);
                }
        }

        // ---- collapse packed partials ----
        float S[4][8];
        #pragma unroll
        for (int rr = 0; rr < 4; ++rr)
            #pragma unroll
            for (int b = 0; b < 8; ++b) {
                float2 t = unpack2(Sp[rr][b]);
                S[rr][b] = t.x + t.y;
            }

        // ---- causal mask inside the diagonal block ----
        if (kb == qi) {
            #pragma unroll
            for (int rr = 0; rr < 4; ++rr) {
                int row = r0 + rr;
                #pragma unroll
                for (int cc = 0; cc < 4; ++cc) {
                    if ((tx << 2) + cc > row)      S[rr][cc]     = -INFINITY;
                    if (32 + (tx << 2) + cc > row) S[rr][4 + cc] = -INFINITY;
                }
            }
        }

        // ---- online softmax (row reduction across the 8 tx lanes) ----
        #pragma unroll
        for (int rr = 0; rr < 4; ++rr) {
            float mx = S[rr][0];
            #pragma unroll
            for (int b = 1; b < 8; ++b) mx = fmaxf(mx, S[rr][b]);
            mx = fmaxf(mx, __shfl_xor_sync(0xffffffffu, mx, 1));
            mx = fmaxf(mx, __shfl_xor_sync(0xffffffffu, mx, 2));
            mx = fmaxf(mx, __shfl_xor_sync(0xffffffffu, mx, 4));
            mx *= sc;
            float mnew = fmaxf(m_i[rr], mx);
            float fac  = __expf(m_i[rr] - mnew);   // 0 on first block (m_i = -inf)
            m_i[rr] = mnew;
            float ls = 0.0f;
            #pragma unroll
            for (int b = 0; b < 8; ++b) {
                float p = __expf(fmaf(S[rr][b], sc, -mnew));
                S[rr][b] = p;
                ls += p;
            }
            l_i[rr] = fmaf(l_i[rr], fac, ls);      // per-thread partial row sum
            unsigned long long facp = pack2(fac);
            #pragma unroll
            for (int c = 0; c < 4; ++c) mul2(Op[rr][c], facp);
        }

        // ---- write P tile (swizzled) ----
        {
            const int sA = ((tx ^ ty) << 2);        // col group tx*4..+3
            const int sB = (((8 | tx) ^ ty) << 2);  // col group 32+tx*4..+3
            #pragma unroll
            for (int rr = 0; rr < 4; ++rr) {
                *reinterpret_cast<float4*>(sP + ((r0 + rr) << 6) + sA) =
                    make_float4(S[rr][0], S[rr][1], S[rr][2], S[rr][3]);
                *reinterpret_cast<float4*>(sP + ((r0 + rr) << 6) + sB) =
                    make_float4(S[rr][4], S[rr][5], S[rr][6], S[rr][7]);
            }
        }
        __syncthreads();

        // ---- GEMM2: O += P * V, packed over column pairs ----
        #pragma unroll
        for (int j4 = 0; j4 < 16; ++j4) {
            float pf[4][4];
            #pragma unroll
            for (int rr = 0; rr < 4; ++rr) {
                float4 t = *reinterpret_cast<const float4*>(
                    sP + ((r0 + rr) << 6) + ((j4 ^ ty) << 2));
                pf[rr][0] = t.x; pf[rr][1] = t.y; pf[rr][2] = t.z; pf[rr][3] = t.w;
            }
            #pragma unroll
            for (int jj = 0; jj < 4; ++jj) {
                int j = (j4 << 2) + jj;
                F4 va, vb;
                va.f = *reinterpret_cast<const float4*>(sV + (j << 6) + (tx << 2));
                vb.f = *reinterpret_cast<const float4*>(sV + (j << 6) + 32 + (tx << 2));
                #pragma unroll
                for (int rr = 0; rr < 4; ++rr) {
                    unsigned long long pp = pack2(pf[rr][jj]);
                    ffma2(Op[rr][0], pp, va.u[0]);
                    ffma2(Op[rr][1], pp, va.u[1]);
                    ffma2(Op[rr][2], pp, vb.u[0]);
                    ffma2(Op[rr][3], pp, vb.u[1]);
                }
            }
        }
    }

    // ---- finalize: reduce l across tx, divide, store [T,H,D] ----
    #pragma unroll
    for (int rr = 0; rr < 4; ++rr) {
        float l = l_i[rr];
        l += __shfl_xor_sync(0xffffffffu, l, 1);
        l += __shfl_xor_sync(0xffffffffu, l, 2);
        l += __shfl_xor_sync(0xffffffffu, l, 4);
        float inv = 1.0f / l;
        float2 o0 = unpack2(Op[rr][0]);
        float2 o1 = unpack2(Op[rr][1]);
        float2 o2 = unpack2(Op[rr][2]);
        float2 o3 = unpack2(Op[rr][3]);
        float* og = out + (size_t)(qi * BSZ + r0 + rr) * HD + h * HEAD;
        float4 oa = make_float4(o0.x * inv, o0.y * inv, o1.x * inv, o1.y * inv);
        float4 ob = make_float4(o2.x * inv, o2.y * inv, o3.x * inv, o3.y * inv);
        *reinterpret_cast<float4*>(og + (tx << 2)) = oa;
        *reinterpret_cast<float4*>(og + 32 + (tx << 2)) = ob;
    }
}

extern "C" void kernel_launch(void* const* d_in, const int* in_sizes, int n_in,
                              void* d_out, int out_size)
{
    const float* q = (const float*)d_in[0];
    const float* k = (const float*)d_in[1];
    const float* v = (const float*)d_in[2];
    // d_in[3] = cu_seqlens_k, fixed [0, 4096] for this problem — unused.
    float* out = (float*)d_out;

    cudaFuncSetAttribute(bs_attn_kernel,
                         cudaFuncAttributeMaxDynamicSharedMemorySize, SMEM_BYTES);
    dim3 grid(NBLK, NHEADS);
    bs_attn_kernel<<<grid, 128, SMEM_BYTES>>>(q, k, v, out);
}

// round 6
// speedup vs baseline: 1.6522x; 1.4691x over previous
#include <cuda_runtime.h>
#include <cstdint>
#include <math.h>

#define NHEADS 16
#define HD     1024            /* floats per token row (16 heads x 64) */
#define LD     68              /* padded SMEM row stride in floats (272B) */
#define COEF   0.18033688011112042f   /* log2(e)/8 */

/* SMEM byte offsets: three 64xLD fp32 tiles */
#define SM_K   0
#define SM_V   (64 * LD * 4)
#define SM_PQ  (2 * 64 * LD * 4)
#define SMEM_BYTES (3 * 64 * LD * 4)   /* 52224 B */

__device__ __forceinline__ uint32_t smem_u32(const void* p) {
    uint32_t a;
    asm("{ .reg .u64 t; cvta.to.shared.u64 t, %1; cvt.u32.u64 %0, t; }" : "=r"(a) : "l"(p));
    return a;
}
__device__ __forceinline__ uint32_t tf32r(float x) {
    uint32_t r; asm("cvt.rna.tf32.f32 %0, %1;" : "=r"(r) : "f"(x)); return r;
}
__device__ __forceinline__ float ex2a(float x) {
    float r; asm("ex2.approx.f32 %0, %1;" : "=f"(r) : "f"(x)); return r;
}
__device__ __forceinline__ void ldsm4(uint32_t* r, uint32_t addr) {
    asm volatile("ldmatrix.sync.aligned.m8n8.x4.shared.b16 {%0,%1,%2,%3}, [%4];"
                 : "=r"(r[0]), "=r"(r[1]), "=r"(r[2]), "=r"(r[3]) : "r"(addr));
}
__device__ __forceinline__ void mma8(float* c, const uint32_t* a, uint32_t b0, uint32_t b1) {
    asm volatile("mma.sync.aligned.m16n8k8.row.col.f32.tf32.tf32.f32 "
                 "{%0,%1,%2,%3}, {%4,%5,%6,%7}, {%8,%9}, {%0,%1,%2,%3};"
                 : "+f"(c[0]), "+f"(c[1]), "+f"(c[2]), "+f"(c[3])
                 : "r"(a[0]), "r"(a[1]), "r"(a[2]), "r"(a[3]), "r"(b0), "r"(b1));
}

__global__ __launch_bounds__(128)
void bs_attn_mma(const float* __restrict__ qg_,
                 const float* __restrict__ kg_,
                 const float* __restrict__ vg_,
                 float* __restrict__ out)
{
    const int qi = 63 - (int)blockIdx.x;      /* heavy blocks first */
    const int h  = (int)blockIdx.y;

    extern __shared__ char sb[];
    const uint32_t smu = smem_u32(sb);
    const int tid  = (int)threadIdx.x;
    const int lane = tid & 31;
    const int w    = tid >> 5;
    const int g    = lane >> 2;               /* row group 0..7 */
    const int t    = lane & 3;

    /* loader mapping: thread -> (token row jq, d-half dh). Conflict-free STS. */
    const int jq = tid & 63;
    const int dh = (tid >> 6) << 5;

    /* ---- stage Q into sPQ (tf32), then pull A fragments to registers ---- */
    {
        const float* qgb = qg_ + (size_t)(qi * 64 + jq) * HD + h * 64 + dh;
        #pragma unroll
        for (int e = 0; e < 8; ++e) {
            float4 v = *reinterpret_cast<const float4*>(qgb + (e << 2));
            uint4 u = make_uint4(tf32r(v.x), tf32r(v.y), tf32r(v.z), tf32r(v.w));
            *reinterpret_cast<uint4*>(sb + SM_PQ + (jq * LD + dh + (e << 2)) * 4) = u;
        }
    }
    __syncthreads();

    uint32_t qa[32];
    {
        const uint32_t rbase = smu + SM_PQ + (uint32_t)((16 * w + (lane & 15)) * LD) * 4;
        #pragma unroll
        for (int s = 0; s < 8; ++s)
            ldsm4(qa + 4 * s, rbase + (uint32_t)(2 * s + (lane >> 4)) * 16);
    }

    /* ---- k-block enumeration: verticals (j≡7-h mod 8, j<=qi-8) + locals ---- */
    const int rv = (23 - h) & 7;
    const int nv = (qi - 8 >= rv) ? (((qi - 8 - rv) >> 3) + 1) : 0;
    const int j0 = (qi - 7 > 0) ? (qi - 7) : 0;
    const int nb = nv + (qi - j0 + 1);

    const int rowj_off  = ((lane >> 4) << 3) + (lane & 7);   /* ldmatrix B-row map */
    const int grp_half  = (lane >> 3) & 1;
    const int row0      = 16 * w + g;

    float oacc[8][4];
    #pragma unroll
    for (int nt = 0; nt < 8; ++nt)
        #pragma unroll
        for (int c = 0; c < 4; ++c) oacc[nt][c] = 0.0f;
    float l0 = 0.0f, l1 = 0.0f;

    for (int it = 0; it < nb; ++it) {
        const int kb = (it < nv) ? (rv + (it << 3)) : (j0 + it - nv);

        /* prefetch K/V into registers (overlaps other warps' GEMM2 tail) */
        const float* kgb = kg_ + (size_t)(kb * 64 + jq) * HD + h * 64 + dh;
        const float* vgb = vg_ + (size_t)(kb * 64 + jq) * HD + h * 64 + dh;
        float4 kr[8], vr[8];
        #pragma unroll
        for (int e = 0; e < 8; ++e) {
            kr[e] = *reinterpret_cast<const float4*>(kgb + (e << 2));
            vr[e] = *reinterpret_cast<const float4*>(vgb + (e << 2));
        }
        __syncthreads();
        #pragma unroll
        for (int e = 0; e < 8; ++e) {
            const int d0 = dh + (e << 2);
            uint4 ku = make_uint4(tf32r(kr[e].x), tf32r(kr[e].y), tf32r(kr[e].z), tf32r(kr[e].w));
            *reinterpret_cast<uint4*>(sb + SM_K + (jq * LD + d0) * 4) = ku;
            /* V transposed: sV[d][j] */
            *reinterpret_cast<uint32_t*>(sb + SM_V + ((d0 + 0) * LD + jq) * 4) = tf32r(vr[e].x);
            *reinterpret_cast<uint32_t*>(sb + SM_V + ((d0 + 1) * LD + jq) * 4) = tf32r(vr[e].y);
            *reinterpret_cast<uint32_t*>(sb + SM_V + ((d0 + 2) * LD + jq) * 4) = tf32r(vr[e].z);
            *reinterpret_cast<uint32_t*>(sb + SM_V + ((d0 + 3) * LD + jq) * 4) = tf32r(vr[e].w);
        }
        __syncthreads();

        /* ---- GEMM1: S = Q @ K^T (warp's 16 rows x 64 cols) ---- */
        float acc[8][4];
        #pragma unroll
        for (int nt = 0; nt < 8; ++nt)
            #pragma unroll
            for (int c = 0; c < 4; ++c) acc[nt][c] = 0.0f;

        #pragma unroll
        for (int s = 0; s < 8; ++s) {
            uint32_t kb4[16];
            #pragma unroll
            for (int ntp = 0; ntp < 4; ++ntp)
                ldsm4(kb4 + 4 * ntp,
                      smu + SM_K + (uint32_t)((16 * ntp + rowj_off) * LD) * 4
                                 + (uint32_t)(2 * s + grp_half) * 16);
            #pragma unroll
            for (int nt = 0; nt < 8; ++nt)
                mma8(acc[nt], qa + 4 * s, kb4[2 * nt], kb4[2 * nt + 1]);
        }

        /* ---- softmax (no max subtraction; scores bounded) + P store ---- */
        const bool diag = (kb == qi);
        #pragma unroll
        for (int nt = 0; nt < 8; ++nt) {
            const int col = 8 * nt + 2 * t;
            float p0 = ex2a(acc[nt][0] * COEF);
            float p1 = ex2a(acc[nt][1] * COEF);
            float p2 = ex2a(acc[nt][2] * COEF);
            float p3 = ex2a(acc[nt][3] * COEF);
            if (diag) {
                if (col     > row0)     p0 = 0.0f;
                if (col + 1 > row0)     p1 = 0.0f;
                if (col     > row0 + 8) p2 = 0.0f;
                if (col + 1 > row0 + 8) p3 = 0.0f;
            }
            l0 += p0 + p1;
            l1 += p2 + p3;
            *reinterpret_cast<uint2*>(sb + SM_PQ + (row0 * LD + col) * 4) =
                make_uint2(tf32r(p0), tf32r(p1));
            *reinterpret_cast<uint2*>(sb + SM_PQ + ((row0 + 8) * LD + col) * 4) =
                make_uint2(tf32r(p2), tf32r(p3));
        }
        __syncwarp();   /* P region is warp-private (own 16 rows) */

        /* ---- GEMM2: O += P @ V ---- */
        #pragma unroll
        for (int ks = 0; ks < 8; ++ks) {
            uint32_t pa[4];
            ldsm4(pa, smu + SM_PQ + (uint32_t)((16 * w + (lane & 15)) * LD) * 4
                                  + (uint32_t)(2 * ks + (lane >> 4)) * 16);
            uint32_t vb4[16];
            #pragma unroll
            for (int ntp = 0; ntp < 4; ++ntp)
                ldsm4(vb4 + 4 * ntp,
                      smu + SM_V + (uint32_t)((16 * ntp + rowj_off) * LD) * 4
                                 + (uint32_t)(2 * ks + grp_half) * 16);
            #pragma unroll
            for (int nt = 0; nt < 8; ++nt)
                mma8(oacc[nt], pa, vb4[2 * nt], vb4[2 * nt + 1]);
        }
    }

    /* ---- finalize: reduce l across the 4 lanes of the row group, store ---- */
    l0 += __shfl_xor_sync(0xffffffffu, l0, 1);
    l0 += __shfl_xor_sync(0xffffffffu, l0, 2);
    l1 += __shfl_xor_sync(0xffffffffu, l1, 1);
    l1 += __shfl_xor_sync(0xffffffffu, l1, 2);
    const float inv0 = 1.0f / l0;
    const float inv1 = 1.0f / l1;

    float* ob0 = out + (size_t)(qi * 64 + row0) * HD + h * 64;
    float* ob1 = ob0 + (size_t)8 * HD;
    #pragma unroll
    for (int nt = 0; nt < 8; ++nt) {
        const int col = 8 * nt + 2 * t;
        *reinterpret_cast<float2*>(ob0 + col) =
            make_float2(oacc[nt][0] * inv0, oacc[nt][1] * inv0);
        *reinterpret_cast<float2*>(ob1 + col) =
            make_float2(oacc[nt][2] * inv1, oacc[nt][3] * inv1);
    }
}

extern "C" void kernel_launch(void* const* d_in, const int* in_sizes, int n_in,
                              void* d_out, int out_size)
{
    const float* q = (const float*)d_in[0];
    const float* k = (const float*)d_in[1];
    const float* v = (const float*)d_in[2];
    /* d_in[3] = cu_seqlens_k, fixed [0, 4096] — unused */
    float* out = (float*)d_out;

    cudaFuncSetAttribute(bs_attn_mma,
                         cudaFuncAttributeMaxDynamicSharedMemorySize, SMEM_BYTES);
    dim3 grid(64, NHEADS);
    bs_attn_mma<<<grid, 128, SMEM_BYTES>>>(q, k, v, out);
}

// round 7
// speedup vs baseline: 2.1841x; 1.3220x over previous
#include <cuda_runtime.h>
#include <cstdint>
#include <math.h>

#define NHEADS 16
#define HD     1024            /* floats per token row (16 heads x 64) */
#define LD     68              /* padded SMEM row stride in floats (272B) */
#define COEF   0.18033688011112042f   /* log2(e)/8 */

/* SMEM byte offsets: double-buffered K (P overwrites active K buffer) + V.
   Q stages through the V region in the prologue. */
#define SM_K0  0
#define SM_K1  (64 * LD * 4)
#define SM_V   (2 * 64 * LD * 4)
#define SMEM_BYTES (3 * 64 * LD * 4)   /* 52224 B */

__device__ __forceinline__ uint32_t smem_u32(const void* p) {
    uint32_t a;
    asm("{ .reg .u64 t; cvta.to.shared.u64 t, %1; cvt.u32.u64 %0, t; }" : "=r"(a) : "l"(p));
    return a;
}
__device__ __forceinline__ uint32_t tf32r(float x) {
    uint32_t r; asm("cvt.rna.tf32.f32 %0, %1;" : "=r"(r) : "f"(x)); return r;
}
__device__ __forceinline__ float ex2a(float x) {
    float r; asm("ex2.approx.f32 %0, %1;" : "=f"(r) : "f"(x)); return r;
}
__device__ __forceinline__ void ldsm4(uint32_t* r, uint32_t addr) {
    asm volatile("ldmatrix.sync.aligned.m8n8.x4.shared.b16 {%0,%1,%2,%3}, [%4];"
                 : "=r"(r[0]), "=r"(r[1]), "=r"(r[2]), "=r"(r[3]) : "r"(addr));
}
__device__ __forceinline__ void mma8(float* c, const uint32_t* a, uint32_t b0, uint32_t b1) {
    asm volatile("mma.sync.aligned.m16n8k8.row.col.f32.tf32.tf32.f32 "
                 "{%0,%1,%2,%3}, {%4,%5,%6,%7}, {%8,%9}, {%0,%1,%2,%3};"
                 : "+f"(c[0]), "+f"(c[1]), "+f"(c[2]), "+f"(c[3])
                 : "r"(a[0]), "r"(a[1]), "r"(a[2]), "r"(a[3]), "r"(b0), "r"(b1));
}
__device__ __forceinline__ void cpa16(uint32_t dst, const void* src) {
    asm volatile("cp.async.cg.shared.global [%0], [%1], 16;" :: "r"(dst), "l"(src) : "memory");
}
#define CPA_COMMIT() asm volatile("cp.async.commit_group;" ::: "memory")
#define CPA_WAIT1()  asm volatile("cp.async.wait_group 1;" ::: "memory")

__global__ __launch_bounds__(128)
void bs_attn_mma(const float* __restrict__ qg_,
                 const float* __restrict__ kg_,
                 const float* __restrict__ vg_,
                 float* __restrict__ out)
{
    const int qi = 63 - (int)blockIdx.x;      /* heavy blocks first */
    const int h  = (int)blockIdx.y;

    extern __shared__ char sb[];
    const uint32_t smu = smem_u32(sb);
    const int tid  = (int)threadIdx.x;
    const int lane = tid & 31;
    const int w    = tid >> 5;
    const int g    = lane >> 2;               /* row group 0..7 */
    const int t    = lane & 3;

    /* loader mapping: thread -> (token row jq, d-half dh) */
    const int jq = tid & 63;
    const int dh = (tid >> 6) << 5;

    /* ---- stage Q (tf32, rna) through sV, pull A fragments to registers ---- */
    {
        const float* qgb = qg_ + (size_t)(qi * 64 + jq) * HD + h * 64 + dh;
        #pragma unroll
        for (int e = 0; e < 8; ++e) {
            float4 v = *reinterpret_cast<const float4*>(qgb + (e << 2));
            uint4 u = make_uint4(tf32r(v.x), tf32r(v.y), tf32r(v.z), tf32r(v.w));
            *reinterpret_cast<uint4*>(sb + SM_V + (jq * LD + dh + (e << 2)) * 4) = u;
        }
    }
    __syncthreads();

    uint32_t qa[32];
    {
        const uint32_t rbase = smu + SM_V + (uint32_t)((16 * w + (lane & 15)) * LD) * 4;
        #pragma unroll
        for (int s = 0; s < 8; ++s)
            ldsm4(qa + 4 * s, rbase + (uint32_t)(2 * s + (lane >> 4)) * 16);
    }

    /* ---- k-block enumeration: verticals (j≡7-h mod 8, j<=qi-8) + locals ---- */
    const int rv = (23 - h) & 7;
    const int nv = (qi - 8 >= rv) ? (((qi - 8 - rv) >> 3) + 1) : 0;
    const int j0 = (qi - 7 > 0) ? (qi - 7) : 0;
    const int nb = nv + (qi - j0 + 1);

    const int rowj_off = ((lane >> 4) << 3) + (lane & 7);   /* ldmatrix B-row map */
    const int grp_half = (lane >> 3) & 1;
    const int row0     = 16 * w + g;

    /* prologue: cp.async K(block 0) into buffer 0 (raw fp32 -> tf32 truncation) */
    {
        const int kb0 = (0 < nv) ? rv : j0;
        const float* kgb = kg_ + (size_t)(kb0 * 64 + jq) * HD + h * 64 + dh;
        const uint32_t kdst = smu + SM_K0 + (uint32_t)((jq * LD + dh) * 4);
        #pragma unroll
        for (int e = 0; e < 8; ++e)
            cpa16(kdst + (e << 4), kgb + (e << 2));
        CPA_COMMIT();
    }

    float oacc[8][4];
    #pragma unroll
    for (int nt = 0; nt < 8; ++nt)
        #pragma unroll
        for (int c = 0; c < 4; ++c) oacc[nt][c] = 0.0f;
    float l0 = 0.0f, l1 = 0.0f;

    for (int it = 0; it < nb; ++it) {
        const int kb = (it < nv) ? (rv + (it << 3)) : (j0 + it - nv);
        const int itn = (it + 1 < nb) ? (it + 1) : it;        /* clamped prefetch */
        const int kbn = (itn < nv) ? (rv + (itn << 3)) : (j0 + itn - nv);

        /* V prefetch into registers (LDG latency overlaps the barrier wait) */
        const float* vgb = vg_ + (size_t)(kb * 64 + jq) * HD + h * 64 + dh;
        float4 vr[8];
        #pragma unroll
        for (int e = 0; e < 8; ++e)
            vr[e] = *reinterpret_cast<const float4*>(vgb + (e << 2));

        __syncthreads();   /* prev GEMM2 (readers of P in other K buf + V) done */

        /* cp.async next K into the other buffer (holds dead P of it-1) */
        {
            const float* kgb = kg_ + (size_t)(kbn * 64 + jq) * HD + h * 64 + dh;
            const uint32_t kdst = smu + (((it + 1) & 1) ? SM_K1 : SM_K0)
                                      + (uint32_t)((jq * LD + dh) * 4);
            #pragma unroll
            for (int e = 0; e < 8; ++e)
                cpa16(kdst + (e << 4), kgb + (e << 2));
            CPA_COMMIT();
        }

        /* V transposed store (rna cvt): sV[d][j] */
        #pragma unroll
        for (int e = 0; e < 8; ++e) {
            const int d0 = dh + (e << 2);
            *reinterpret_cast<uint32_t*>(sb + SM_V + ((d0 + 0) * LD + jq) * 4) = tf32r(vr[e].x);
            *reinterpret_cast<uint32_t*>(sb + SM_V + ((d0 + 1) * LD + jq) * 4) = tf32r(vr[e].y);
            *reinterpret_cast<uint32_t*>(sb + SM_V + ((d0 + 2) * LD + jq) * 4) = tf32r(vr[e].z);
            *reinterpret_cast<uint32_t*>(sb + SM_V + ((d0 + 3) * LD + jq) * 4) = tf32r(vr[e].w);
        }
        CPA_WAIT1();       /* K(it) resident (<=1 group outstanding = K(it+1)) */
        __syncthreads();

        const uint32_t kbase = smu + ((it & 1) ? SM_K1 : SM_K0);

        /* ---- GEMM1: S = Q @ K^T (warp's 16 rows x 64 cols) ---- */
        float acc[8][4];
        #pragma unroll
        for (int nt = 0; nt < 8; ++nt)
            #pragma unroll
            for (int c = 0; c < 4; ++c) acc[nt][c] = 0.0f;

        #pragma unroll
        for (int s = 0; s < 8; ++s) {
            uint32_t kb4[16];
            #pragma unroll
            for (int ntp = 0; ntp < 4; ++ntp)
                ldsm4(kb4 + 4 * ntp,
                      kbase + (uint32_t)((16 * ntp + rowj_off) * LD) * 4
                            + (uint32_t)(2 * s + grp_half) * 16);
            #pragma unroll
            for (int nt = 0; nt < 8; ++nt)
                mma8(acc[nt], qa + 4 * s, kb4[2 * nt], kb4[2 * nt + 1]);
        }

        /* ---- softmax in regs (no max subtraction; scores bounded) ---- */
        const bool diag = (kb == qi);
        #pragma unroll
        for (int nt = 0; nt < 8; ++nt) {
            const int col = 8 * nt + 2 * t;
            float p0 = ex2a(acc[nt][0] * COEF);
            float p1 = ex2a(acc[nt][1] * COEF);
            float p2 = ex2a(acc[nt][2] * COEF);
            float p3 = ex2a(acc[nt][3] * COEF);
            if (diag) {
                if (col     > row0)     p0 = 0.0f;
                if (col + 1 > row0)     p1 = 0.0f;
                if (col     > row0 + 8) p2 = 0.0f;
                if (col + 1 > row0 + 8) p3 = 0.0f;
            }
            l0 += p0 + p1;
            l1 += p2 + p3;
            acc[nt][0] = p0; acc[nt][1] = p1; acc[nt][2] = p2; acc[nt][3] = p3;
        }

        __syncthreads();   /* all warps finished reading K(it) */

        /* ---- P store (rna tf32) into the consumed K buffer ---- */
        #pragma unroll
        for (int nt = 0; nt < 8; ++nt) {
            const int col = 8 * nt + 2 * t;
            *reinterpret_cast<uint2*>(sb + (kbase - smu) + (row0 * LD + col) * 4) =
                make_uint2(tf32r(acc[nt][0]), tf32r(acc[nt][1]));
            *reinterpret_cast<uint2*>(sb + (kbase - smu) + ((row0 + 8) * LD + col) * 4) =
                make_uint2(tf32r(acc[nt][2]), tf32r(acc[nt][3]));
        }
        __syncwarp();      /* P rows are warp-private */

        /* ---- GEMM2: O += P @ V ---- */
        #pragma unroll
        for (int ks = 0; ks < 8; ++ks) {
            uint32_t pa[4];
            ldsm4(pa, kbase + (uint32_t)((16 * w + (lane & 15)) * LD) * 4
                            + (uint32_t)(2 * ks + (lane >> 4)) * 16);
            uint32_t vb4[16];
            #pragma unroll
            for (int ntp = 0; ntp < 4; ++ntp)
                ldsm4(vb4 + 4 * ntp,
                      smu + SM_V + (uint32_t)((16 * ntp + rowj_off) * LD) * 4
                                 + (uint32_t)(2 * ks + grp_half) * 16);
            #pragma unroll
            for (int nt = 0; nt < 8; ++nt)
                mma8(oacc[nt], pa, vb4[2 * nt], vb4[2 * nt + 1]);
        }
    }

    /* ---- finalize: reduce l across the 4 lanes of the row group, store ---- */
    l0 += __shfl_xor_sync(0xffffffffu, l0, 1);
    l0 += __shfl_xor_sync(0xffffffffu, l0, 2);
    l1 += __shfl_xor_sync(0xffffffffu, l1, 1);
    l1 += __shfl_xor_sync(0xffffffffu, l1, 2);
    const float inv0 = 1.0f / l0;
    const float inv1 = 1.0f / l1;

    float* ob0 = out + (size_t)(qi * 64 + row0) * HD + h * 64;
    float* ob1 = ob0 + (size_t)8 * HD;
    #pragma unroll
    for (int nt = 0; nt < 8; ++nt) {
        const int col = 8 * nt + 2 * t;
        *reinterpret_cast<float2*>(ob0 + col) =
            make_float2(oacc[nt][0] * inv0, oacc[nt][1] * inv0);
        *reinterpret_cast<float2*>(ob1 + col) =
            make_float2(oacc[nt][2] * inv1, oacc[nt][3] * inv1);
    }
}

extern "C" void kernel_launch(void* const* d_in, const int* in_sizes, int n_in,
                              void* d_out, int out_size)
{
    const float* q = (const float*)d_in[0];
    const float* k = (const float*)d_in[1];
    const float* v = (const float*)d_in[2];
    /* d_in[3] = cu_seqlens_k, fixed [0, 4096] — unused */
    float* out = (float*)d_out;

    cudaFuncSetAttribute(bs_attn_mma,
                         cudaFuncAttributeMaxDynamicSharedMemorySize, SMEM_BYTES);
    dim3 grid(64, NHEADS);
    bs_attn_mma<<<grid, 128, SMEM_BYTES>>>(q, k, v, out);
}

// round 9
// speedup vs baseline: 2.2525x; 1.0313x over previous
#include <cuda_runtime.h>
#include <cstdint>
#include <math.h>

#define NHEADS 16
#define HD     1024            /* floats per token row (16 heads x 64) */
#define LD     68              /* padded SMEM row stride in floats (272B) */
#define COEF   0.18033688011112042f   /* log2(e)/8 */

/* SMEM: double-buffered K + V (64 rows each) + dedicated 128-row P.
   Q (128 rows) stages through P in the prologue. */
#define SM_K0  0
#define SM_K1  (64 * LD * 4)
#define SM_V   (2 * 64 * LD * 4)
#define SM_P   (3 * 64 * LD * 4)
#define SMEM_BYTES ((3 * 64 + 128) * LD * 4)   /* 87040 B */

__device__ __forceinline__ uint32_t smem_u32(const void* p) {
    uint32_t a;
    asm("{ .reg .u64 t; cvta.to.shared.u64 t, %1; cvt.u32.u64 %0, t; }" : "=r"(a) : "l"(p));
    return a;
}
__device__ __forceinline__ uint32_t tf32r(float x) {
    uint32_t r; asm("cvt.rna.tf32.f32 %0, %1;" : "=r"(r) : "f"(x)); return r;
}
__device__ __forceinline__ float ex2a(float x) {
    float r; asm("ex2.approx.f32 %0, %1;" : "=f"(r) : "f"(x)); return r;
}
__device__ __forceinline__ void ldsm4(uint32_t* r, uint32_t addr) {
    asm volatile("ldmatrix.sync.aligned.m8n8.x4.shared.b16 {%0,%1,%2,%3}, [%4];"
                 : "=r"(r[0]), "=r"(r[1]), "=r"(r[2]), "=r"(r[3]) : "r"(addr));
}
__device__ __forceinline__ void mma8(float* c, const uint32_t* a, uint32_t b0, uint32_t b1) {
    asm volatile("mma.sync.aligned.m16n8k8.row.col.f32.tf32.tf32.f32 "
                 "{%0,%1,%2,%3}, {%4,%5,%6,%7}, {%8,%9}, {%0,%1,%2,%3};"
                 : "+f"(c[0]), "+f"(c[1]), "+f"(c[2]), "+f"(c[3])
                 : "r"(a[0]), "r"(a[1]), "r"(a[2]), "r"(a[3]), "r"(b0), "r"(b1));
}
__device__ __forceinline__ void cpa16(uint32_t dst, const void* src) {
    asm volatile("cp.async.cg.shared.global [%0], [%1], 16;" :: "r"(dst), "l"(src) : "memory");
}
#define CPA_COMMIT() asm volatile("cp.async.commit_group;" ::: "memory")
#define CPA_WAIT1()  asm volatile("cp.async.wait_group 1;" ::: "memory")

__global__ __launch_bounds__(128)
void bs_attn_mma(const float* __restrict__ qg_,
                 const float* __restrict__ kg_,
                 const float* __restrict__ vg_,
                 float* __restrict__ out)
{
    const int pr  = 31 - (int)blockIdx.x;     /* heavy pairs first */
    const int qlo = pr << 1;                  /* CTA covers q-blocks qlo, qlo+1 */
    const int h   = (int)blockIdx.y;

    extern __shared__ char sb[];
    const uint32_t smu = smem_u32(sb);
    const int tid  = (int)threadIdx.x;
    const int lane = tid & 31;
    const int w    = tid >> 5;
    const int g    = lane >> 2;
    const int t    = lane & 3;

    /* loader mapping: thread -> (token row jq, d-half dh) */
    const int jq = tid & 63;
    const int dh = (tid >> 6) << 5;

    /* ---- stage Q (128 rows, tf32 rna) through SM_P, pull A frags ---- */
    #pragma unroll
    for (int half = 0; half < 2; ++half) {
        const int row = (half << 6) + jq;
        const float* qgb = qg_ + (size_t)(qlo * 64 + row) * HD + h * 64 + dh;
        #pragma unroll
        for (int e = 0; e < 8; ++e) {
            float4 v = *reinterpret_cast<const float4*>(qgb + (e << 2));
            uint4 u = make_uint4(tf32r(v.x), tf32r(v.y), tf32r(v.z), tf32r(v.w));
            *reinterpret_cast<uint4*>(sb + SM_P + (row * LD + dh + (e << 2)) * 4) = u;
        }
    }
    __syncthreads();

    uint32_t qa[2][32];
    #pragma unroll
    for (int tt = 0; tt < 2; ++tt) {
        const uint32_t rbase = smu + SM_P
            + (uint32_t)((32 * w + 16 * tt + (lane & 15)) * LD) * 4;
        #pragma unroll
        for (int s = 0; s < 8; ++s)
            ldsm4(qa[tt] + 4 * s, rbase + (uint32_t)(2 * s + (lane >> 4)) * 16);
    }

    /* ---- k-block enumeration for the pair ---- */
    const int rv  = (7 - h) & 7;
    const int nv  = (qlo - 8 >= rv) ? (((qlo - 8 - rv) >> 3) + 1) : 0;
    const int j0  = (qlo - 7 > 0) ? (qlo - 7) : 0;
    const int qhi = qlo + 1;
    const int nb  = nv + (qhi - j0 + 1);

    const int qbw = qlo + (w >> 1);           /* this warp's q-block */
    const int rowj_off = ((lane >> 4) << 3) + (lane & 7);
    const int grp_half = (lane >> 3) & 1;

    /* prologue: cp.async K(first block) into buffer 0 */
    {
        const int kb0 = (0 < nv) ? rv : j0;
        const float* kgb = kg_ + (size_t)(kb0 * 64 + jq) * HD + h * 64 + dh;
        const uint32_t kdst = smu + SM_K0 + (uint32_t)((jq * LD + dh) * 4);
        #pragma unroll
        for (int e = 0; e < 8; ++e)
            cpa16(kdst + (e << 4), kgb + (e << 2));
        CPA_COMMIT();
    }

    float oacc[2][8][4];
    #pragma unroll
    for (int tt = 0; tt < 2; ++tt)
        #pragma unroll
        for (int nt = 0; nt < 8; ++nt)
            #pragma unroll
            for (int c = 0; c < 4; ++c) oacc[tt][nt][c] = 0.0f;
    float lsum[4] = {0.0f, 0.0f, 0.0f, 0.0f};

    for (int it = 0; it < nb; ++it) {
        const int kb  = (it < nv) ? (rv + (it << 3)) : (j0 + it - nv);
        const int itn = (it + 1 < nb) ? (it + 1) : it;
        const int kbn = (itn < nv) ? (rv + (itn << 3)) : (j0 + itn - nv);

        /* V prefetch into registers */
        const float* vgb = vg_ + (size_t)(kb * 64 + jq) * HD + h * 64 + dh;
        float4 vr[8];
        #pragma unroll
        for (int e = 0; e < 8; ++e)
            vr[e] = *reinterpret_cast<const float4*>(vgb + (e << 2));

        __syncthreads();   /* prev iter: GEMM1 readers of K(it-1), GEMM2 readers of V done */

        /* cp.async next K into the other buffer */
        {
            const float* kgb = kg_ + (size_t)(kbn * 64 + jq) * HD + h * 64 + dh;
            const uint32_t kdst = smu + (((it + 1) & 1) ? SM_K1 : SM_K0)
                                      + (uint32_t)((jq * LD + dh) * 4);
            #pragma unroll
            for (int e = 0; e < 8; ++e)
                cpa16(kdst + (e << 4), kgb + (e << 2));
            CPA_COMMIT();
        }

        /* V transposed store (rna cvt): sV[d][j] */
        #pragma unroll
        for (int e = 0; e < 8; ++e) {
            const int d0 = dh + (e << 2);
            *reinterpret_cast<uint32_t*>(sb + SM_V + ((d0 + 0) * LD + jq) * 4) = tf32r(vr[e].x);
            *reinterpret_cast<uint32_t*>(sb + SM_V + ((d0 + 1) * LD + jq) * 4) = tf32r(vr[e].y);
            *reinterpret_cast<uint32_t*>(sb + SM_V + ((d0 + 2) * LD + jq) * 4) = tf32r(vr[e].z);
            *reinterpret_cast<uint32_t*>(sb + SM_V + ((d0 + 3) * LD + jq) * 4) = tf32r(vr[e].w);
        }
        CPA_WAIT1();       /* K(it) resident */
        __syncthreads();   /* K(it) + V(it) visible to all warps */

        const uint32_t kbase = smu + ((it & 1) ? SM_K1 : SM_K0);

        /* warp-uniform predicates for this warp's q-block */
        const bool alw  = (kb <= qbw) && (((qbw - kb) < 8) || ((kb & 7) == rv));
        const bool diag = (kb == qbw);

        if (alw) {
            float acc[2][8][4];
            #pragma unroll
            for (int tt = 0; tt < 2; ++tt)
                #pragma unroll
                for (int nt = 0; nt < 8; ++nt)
                    #pragma unroll
                    for (int c = 0; c < 4; ++c) acc[tt][nt][c] = 0.0f;

            /* GEMM1: both m16 tiles share each K fragment load */
            #pragma unroll
            for (int s = 0; s < 8; ++s) {
                uint32_t kb4[16];
                #pragma unroll
                for (int ntp = 0; ntp < 4; ++ntp)
                    ldsm4(kb4 + 4 * ntp,
                          kbase + (uint32_t)((16 * ntp + rowj_off) * LD) * 4
                                + (uint32_t)(2 * s + grp_half) * 16);
                #pragma unroll
                for (int nt = 0; nt < 8; ++nt) {
                    mma8(acc[0][nt], qa[0] + 4 * s, kb4[2 * nt], kb4[2 * nt + 1]);
                    mma8(acc[1][nt], qa[1] + 4 * s, kb4[2 * nt], kb4[2 * nt + 1]);
                }
            }

            /* softmax (no max subtraction; scores bounded) + P store */
            #pragma unroll
            for (int tt = 0; tt < 2; ++tt) {
                const int r0  = 32 * w + 16 * tt + g;   /* CTA row (P row) */
                const int ri0 = r0 & 63;                /* row within q-block */
                #pragma unroll
                for (int nt = 0; nt < 8; ++nt) {
                    const int col = 8 * nt + 2 * t;
                    float p0 = ex2a(acc[tt][nt][0] * COEF);
                    float p1 = ex2a(acc[tt][nt][1] * COEF);
                    float p2 = ex2a(acc[tt][nt][2] * COEF);
                    float p3 = ex2a(acc[tt][nt][3] * COEF);
                    if (diag) {
                        if (col     > ri0)     p0 = 0.0f;
                        if (col + 1 > ri0)     p1 = 0.0f;
                        if (col     > ri0 + 8) p2 = 0.0f;
                        if (col + 1 > ri0 + 8) p3 = 0.0f;
                    }
                    lsum[2 * tt]     += p0 + p1;
                    lsum[2 * tt + 1] += p2 + p3;
                    *reinterpret_cast<uint2*>(sb + SM_P + (r0 * LD + col) * 4) =
                        make_uint2(tf32r(p0), tf32r(p1));
                    *reinterpret_cast<uint2*>(sb + SM_P + ((r0 + 8) * LD + col) * 4) =
                        make_uint2(tf32r(p2), tf32r(p3));
                }
            }
            __syncwarp();  /* P rows are warp-private */

            /* GEMM2: O += P @ V, both tiles share each V fragment load */
            #pragma unroll
            for (int ks = 0; ks < 8; ++ks) {
                uint32_t pa0[4], pa1[4];
                ldsm4(pa0, smu + SM_P + (uint32_t)((32 * w + (lane & 15)) * LD) * 4
                                      + (uint32_t)(2 * ks + (lane >> 4)) * 16);
                ldsm4(pa1, smu + SM_P + (uint32_t)((32 * w + 16 + (lane & 15)) * LD) * 4
                                      + (uint32_t)(2 * ks + (lane >> 4)) * 16);
                uint32_t vb4[16];
                #pragma unroll
                for (int ntp = 0; ntp < 4; ++ntp)
                    ldsm4(vb4 + 4 * ntp,
                          smu + SM_V + (uint32_t)((16 * ntp + rowj_off) * LD) * 4
                                     + (uint32_t)(2 * ks + grp_half) * 16);
                #pragma unroll
                for (int nt = 0; nt < 8; ++nt) {
                    mma8(oacc[0][nt], pa0, vb4[2 * nt], vb4[2 * nt + 1]);
                    mma8(oacc[1][nt], pa1, vb4[2 * nt], vb4[2 * nt + 1]);
                }
            }
        }
    }

    /* ---- finalize ---- */
    #pragma unroll
    for (int i = 0; i < 4; ++i) {
        lsum[i] += __shfl_xor_sync(0xffffffffu, lsum[i], 1);
        lsum[i] += __shfl_xor_sync(0xffffffffu, lsum[i], 2);
    }
    #pragma unroll
    for (int tt = 0; tt < 2; ++tt) {
        const float inv0 = 1.0f / lsum[2 * tt];
        const float inv1 = 1.0f / lsum[2 * tt + 1];
        const int r0 = 32 * w + 16 * tt + g;
        float* ob0 = out + (size_t)(qlo * 64 + r0) * HD + h * 64;
        float* ob1 = ob0 + (size_t)8 * HD;
        #pragma unroll
        for (int nt = 0; nt < 8; ++nt) {
            const int col = 8 * nt + 2 * t;
            *reinterpret_cast<float2*>(ob0 + col) =
                make_float2(oacc[tt][nt][0] * inv0, oacc[tt][nt][1] * inv0);
            *reinterpret_cast<float2*>(ob1 + col) =
                make_float2(oacc[tt][nt][2] * inv1, oacc[tt][nt][3] * inv1);
        }
    }
}

extern "C" void kernel_launch(void* const* d_in, const int* in_sizes, int n_in,
                              void* d_out, int out_size)
{
    const float* q = (const float*)d_in[0];
    const float* k = (const float*)d_in[1];
    const float* v = (const float*)d_in[2];
    /* d_in[3] = cu_seqlens_k, fixed [0, 4096] — unused */
    float* out = (float*)d_out;

    cudaFuncSetAttribute(bs_attn_mma,
                         cudaFuncAttributeMaxDynamicSharedMemorySize, SMEM_BYTES);
    dim3 grid(32, NHEADS);
    bs_attn_mma<<<grid, 128, SMEM_BYTES>>>(q, k, v, out);
}

// round 10
// speedup vs baseline: 2.3588x; 1.0472x over previous
#include <cuda_runtime.h>
#include <cstdint>
#include <math.h>

#define NHEADS 16
#define HD     1024            /* floats per token row (16 heads x 64) */
#define LD     68              /* padded SMEM row stride in floats (272B) */
#define COEF   0.18033688011112042f   /* log2(e)/8 */

/* SMEM: double-buffered K + V (64 rows each) + dedicated 128-row P.
   Q (128 rows) stages through P in the prologue. */
#define SM_K0  0
#define SM_K1  (64 * LD * 4)
#define SM_V   (2 * 64 * LD * 4)
#define SM_P   (3 * 64 * LD * 4)
#define SMEM_BYTES ((3 * 64 + 128) * LD * 4)   /* 87040 B */

__device__ __forceinline__ uint32_t smem_u32(const void* p) {
    uint32_t a;
    asm("{ .reg .u64 t; cvta.to.shared.u64 t, %1; cvt.u32.u64 %0, t; }" : "=r"(a) : "l"(p));
    return a;
}
__device__ __forceinline__ uint32_t tf32r(float x) {
    uint32_t r; asm("cvt.rna.tf32.f32 %0, %1;" : "=r"(r) : "f"(x)); return r;
}
__device__ __forceinline__ float ex2a(float x) {
    float r; asm("ex2.approx.f32 %0, %1;" : "=f"(r) : "f"(x)); return r;
}
__device__ __forceinline__ void ldsm4(uint32_t* r, uint32_t addr) {
    asm volatile("ldmatrix.sync.aligned.m8n8.x4.shared.b16 {%0,%1,%2,%3}, [%4];"
                 : "=r"(r[0]), "=r"(r[1]), "=r"(r[2]), "=r"(r[3]) : "r"(addr));
}
__device__ __forceinline__ void mma8(float* c, const uint32_t* a, uint32_t b0, uint32_t b1) {
    asm volatile("mma.sync.aligned.m16n8k8.row.col.f32.tf32.tf32.f32 "
                 "{%0,%1,%2,%3}, {%4,%5,%6,%7}, {%8,%9}, {%0,%1,%2,%3};"
                 : "+f"(c[0]), "+f"(c[1]), "+f"(c[2]), "+f"(c[3])
                 : "r"(a[0]), "r"(a[1]), "r"(a[2]), "r"(a[3]), "r"(b0), "r"(b1));
}
__device__ __forceinline__ void cpa16(uint32_t dst, const void* src) {
    asm volatile("cp.async.cg.shared.global [%0], [%1], 16;" :: "r"(dst), "l"(src) : "memory");
}
#define CPA_COMMIT() asm volatile("cp.async.commit_group;" ::: "memory")
#define CPA_WAIT1()  asm volatile("cp.async.wait_group 1;" ::: "memory")

__global__ __launch_bounds__(256, 2)
void bs_attn_mma(const float* __restrict__ qg_,
                 const float* __restrict__ kg_,
                 const float* __restrict__ vg_,
                 float* __restrict__ out)
{
    const int pr  = 31 - (int)blockIdx.x;     /* heavy pairs first */
    const int qlo = pr << 1;                  /* CTA covers q-blocks qlo, qlo+1 */
    const int h   = (int)blockIdx.y;

    extern __shared__ char sb[];
    const uint32_t smu = smem_u32(sb);
    const int tid  = (int)threadIdx.x;
    const int lane = tid & 31;
    const int w    = tid >> 5;                /* 8 warps, warp owns rows 16w..16w+15 */
    const int g    = lane >> 2;
    const int t    = lane & 3;

    /* loader mapping: thread -> (token row jq, d-group dg of 16 floats) */
    const int jq = tid & 63;
    const int dg = (tid >> 6) << 4;           /* 0,16,32,48 */

    /* ---- stage Q (128 rows, tf32 rna) through SM_P ---- */
    #pragma unroll
    for (int e = 0; e < 8; ++e) {
        const int idx = (e << 8) + tid;       /* 0..2047 float4 groups */
        const int row = idx >> 4, d4 = idx & 15;
        const float* qgb = qg_ + (size_t)(qlo * 64 + row) * HD + h * 64 + (d4 << 2);
        float4 v = *reinterpret_cast<const float4*>(qgb);
        uint4 u = make_uint4(tf32r(v.x), tf32r(v.y), tf32r(v.z), tf32r(v.w));
        *reinterpret_cast<uint4*>(sb + SM_P + (row * LD + (d4 << 2)) * 4) = u;
    }
    __syncthreads();

    uint32_t qa[32];
    {
        const uint32_t rbase = smu + SM_P + (uint32_t)((16 * w + (lane & 15)) * LD) * 4;
        #pragma unroll
        for (int s = 0; s < 8; ++s)
            ldsm4(qa + 4 * s, rbase + (uint32_t)(2 * s + (lane >> 4)) * 16);
    }

    /* ---- k-block enumeration for the pair ---- */
    const int rv  = (7 - h) & 7;
    const int nv  = (qlo - 8 >= rv) ? (((qlo - 8 - rv) >> 3) + 1) : 0;
    const int j0  = (qlo - 7 > 0) ? (qlo - 7) : 0;
    const int nb  = nv + (qlo + 2 - j0);

    const int qbw = qlo + (w >> 2);           /* warps 0-3: qlo, 4-7: qlo+1 */
    const int rowj_off = ((lane >> 4) << 3) + (lane & 7);
    const int grp_half = (lane >> 3) & 1;

    /* prologue: cp.async K(first block) into buffer 0 */
    {
        const int kb0 = (0 < nv) ? rv : j0;
        const float* kgb = kg_ + (size_t)(kb0 * 64 + jq) * HD + h * 64 + dg;
        const uint32_t kdst = smu + SM_K0 + (uint32_t)((jq * LD + dg) * 4);
        #pragma unroll
        for (int e = 0; e < 4; ++e)
            cpa16(kdst + (e << 4), kgb + (e << 2));
        CPA_COMMIT();
    }

    float oacc[8][4];
    #pragma unroll
    for (int nt = 0; nt < 8; ++nt)
        #pragma unroll
        for (int c = 0; c < 4; ++c) oacc[nt][c] = 0.0f;
    float l0 = 0.0f, l1 = 0.0f;

    for (int it = 0; it < nb; ++it) {
        const int kb  = (it < nv) ? (rv + (it << 3)) : (j0 + it - nv);
        const int itn = (it + 1 < nb) ? (it + 1) : it;
        const int kbn = (itn < nv) ? (rv + (itn << 3)) : (j0 + itn - nv);

        /* V prefetch into registers */
        const float* vgb = vg_ + (size_t)(kb * 64 + jq) * HD + h * 64 + dg;
        float4 vr[4];
        #pragma unroll
        for (int e = 0; e < 4; ++e)
            vr[e] = *reinterpret_cast<const float4*>(vgb + (e << 2));

        __syncthreads();   /* prev iter GEMM1/GEMM2 readers of K(it-1)/V done */

        /* cp.async next K into the other buffer */
        {
            const float* kgb = kg_ + (size_t)(kbn * 64 + jq) * HD + h * 64 + dg;
            const uint32_t kdst = smu + (((it + 1) & 1) ? SM_K1 : SM_K0)
                                      + (uint32_t)((jq * LD + dg) * 4);
            #pragma unroll
            for (int e = 0; e < 4; ++e)
                cpa16(kdst + (e << 4), kgb + (e << 2));
            CPA_COMMIT();
        }

        /* V transposed store (rna cvt): sV[d][j] */
        #pragma unroll
        for (int e = 0; e < 4; ++e) {
            const int d0 = dg + (e << 2);
            *reinterpret_cast<uint32_t*>(sb + SM_V + ((d0 + 0) * LD + jq) * 4) = tf32r(vr[e].x);
            *reinterpret_cast<uint32_t*>(sb + SM_V + ((d0 + 1) * LD + jq) * 4) = tf32r(vr[e].y);
            *reinterpret_cast<uint32_t*>(sb + SM_V + ((d0 + 2) * LD + jq) * 4) = tf32r(vr[e].z);
            *reinterpret_cast<uint32_t*>(sb + SM_V + ((d0 + 3) * LD + jq) * 4) = tf32r(vr[e].w);
        }
        CPA_WAIT1();       /* K(it) resident */
        __syncthreads();   /* K(it) + V(it) visible */

        const uint32_t kbase = smu + ((it & 1) ? SM_K1 : SM_K0);

        /* warp-uniform predicates for this warp's q-block */
        const bool alw  = (kb <= qbw) && (((qbw - kb) < 8) || ((kb & 7) == rv));
        const bool diag = (kb == qbw);

        if (alw) {
            float acc[8][4];
            #pragma unroll
            for (int nt = 0; nt < 8; ++nt)
                #pragma unroll
                for (int c = 0; c < 4; ++c) acc[nt][c] = 0.0f;

            /* GEMM1: S = Q @ K^T (16 rows x 64 cols) */
            #pragma unroll
            for (int s = 0; s < 8; ++s) {
                uint32_t kb4[16];
                #pragma unroll
                for (int ntp = 0; ntp < 4; ++ntp)
                    ldsm4(kb4 + 4 * ntp,
                          kbase + (uint32_t)((16 * ntp + rowj_off) * LD) * 4
                                + (uint32_t)(2 * s + grp_half) * 16);
                #pragma unroll
                for (int nt = 0; nt < 8; ++nt)
                    mma8(acc[nt], qa + 4 * s, kb4[2 * nt], kb4[2 * nt + 1]);
            }

            /* softmax (no max subtraction; scores bounded) + P store */
            const int r0  = 16 * w + g;         /* CTA row (P row) */
            const int ri0 = r0 & 63;            /* row within q-block */
            #pragma unroll
            for (int nt = 0; nt < 8; ++nt) {
                const int col = 8 * nt + 2 * t;
                float p0 = ex2a(acc[nt][0] * COEF);
                float p1 = ex2a(acc[nt][1] * COEF);
                float p2 = ex2a(acc[nt][2] * COEF);
                float p3 = ex2a(acc[nt][3] * COEF);
                if (diag) {
                    if (col     > ri0)     p0 = 0.0f;
                    if (col + 1 > ri0)     p1 = 0.0f;
                    if (col     > ri0 + 8) p2 = 0.0f;
                    if (col + 1 > ri0 + 8) p3 = 0.0f;
                }
                l0 += p0 + p1;
                l1 += p2 + p3;
                *reinterpret_cast<uint2*>(sb + SM_P + (r0 * LD + col) * 4) =
                    make_uint2(tf32r(p0), tf32r(p1));
                *reinterpret_cast<uint2*>(sb + SM_P + ((r0 + 8) * LD + col) * 4) =
                    make_uint2(tf32r(p2), tf32r(p3));
            }
            __syncwarp();  /* P rows are warp-private */

            /* GEMM2: O += P @ V */
            #pragma unroll
            for (int ks = 0; ks < 8; ++ks) {
                uint32_t pa[4];
                ldsm4(pa, smu + SM_P + (uint32_t)((16 * w + (lane & 15)) * LD) * 4
                                     + (uint32_t)(2 * ks + (lane >> 4)) * 16);
                uint32_t vb4[16];
                #pragma unroll
                for (int ntp = 0; ntp < 4; ++ntp)
                    ldsm4(vb4 + 4 * ntp,
                          smu + SM_V + (uint32_t)((16 * ntp + rowj_off) * LD) * 4
                                     + (uint32_t)(2 * ks + grp_half) * 16);
                #pragma unroll
                for (int nt = 0; nt < 8; ++nt)
                    mma8(oacc[nt], pa, vb4[2 * nt], vb4[2 * nt + 1]);
            }
        }
    }

    /* ---- finalize: reduce l across the 4 lanes of the row group, store ---- */
    l0 += __shfl_xor_sync(0xffffffffu, l0, 1);
    l0 += __shfl_xor_sync(0xffffffffu, l0, 2);
    l1 += __shfl_xor_sync(0xffffffffu, l1, 1);
    l1 += __shfl_xor_sync(0xffffffffu, l1, 2);
    const float inv0 = 1.0f / l0;
    const float inv1 = 1.0f / l1;

    const int r0 = 16 * w + g;
    float* ob0 = out + (size_t)(qlo * 64 + r0) * HD + h * 64;
    float* ob1 = ob0 + (size_t)8 * HD;
    #pragma unroll
    for (int nt = 0; nt < 8; ++nt) {
        const int col = 8 * nt + 2 * t;
        *reinterpret_cast<float2*>(ob0 + col) =
            make_float2(oacc[nt][0] * inv0, oacc[nt][1] * inv0);
        *reinterpret_cast<float2*>(ob1 + col) =
            make_float2(oacc[nt][2] * inv1, oacc[nt][3] * inv1);
    }
}

extern "C" void kernel_launch(void* const* d_in, const int* in_sizes, int n_in,
                              void* d_out, int out_size)
{
    const float* q = (const float*)d_in[0];
    const float* k = (const float*)d_in[1];
    const float* v = (const float*)d_in[2];
    /* d_in[3] = cu_seqlens_k, fixed [0, 4096] — unused */
    float* out = (float*)d_out;

    cudaFuncSetAttribute(bs_attn_mma,
                         cudaFuncAttributeMaxDynamicSharedMemorySize, SMEM_BYTES);
    dim3 grid(32, NHEADS);
    bs_attn_mma<<<grid, 256, SMEM_BYTES>>>(q, k, v, out);
}

// round 11
// speedup vs baseline: 2.6771x; 1.1349x over previous
#include <cuda_runtime.h>
#include <cstdint>
#include <math.h>

#define NHEADS 16
#define HD     1024            /* floats per token row (16 heads x 64) */
#define LD     68              /* fp32 SMEM row stride (272B) — K/Q tiles */
#define LDHB   144             /* fp16 SMEM row stride in BYTES (72 halfs) */
#define COEF   0.18033688011112042f   /* log2(e)/8 */
#define ONESH  0x3C003C00u     /* f16x2 (1.0, 1.0) */

/* SMEM: double-buffered fp32 K + fp16 V (64 rows) + fp16 P (128 rows).
   Q stages through K0+K1 in the prologue. */
#define SM_K0  0
#define SM_K1  (64 * LD * 4)               /* 17408 */
#define SM_V   (2 * 64 * LD * 4)           /* 34816 */
#define SM_P   (SM_V + 64 * LDHB)          /* 44032 */
#define SMEM_BYTES (SM_P + 128 * LDHB)     /* 62464 B */

__device__ __forceinline__ uint32_t smem_u32(const void* p) {
    uint32_t a;
    asm("{ .reg .u64 t; cvta.to.shared.u64 t, %1; cvt.u32.u64 %0, t; }" : "=r"(a) : "l"(p));
    return a;
}
__device__ __forceinline__ uint32_t tf32r(float x) {
    uint32_t r; asm("cvt.rna.tf32.f32 %0, %1;" : "=r"(r) : "f"(x)); return r;
}
__device__ __forceinline__ uint32_t f16x2(float hi, float lo) {
    uint32_t r; asm("cvt.rn.f16x2.f32 %0, %1, %2;" : "=r"(r) : "f"(hi), "f"(lo)); return r;
}
__device__ __forceinline__ float ex2a(float x) {
    float r; asm("ex2.approx.f32 %0, %1;" : "=f"(r) : "f"(x)); return r;
}
__device__ __forceinline__ void ldsm4(uint32_t* r, uint32_t addr) {
    asm volatile("ldmatrix.sync.aligned.m8n8.x4.shared.b16 {%0,%1,%2,%3}, [%4];"
                 : "=r"(r[0]), "=r"(r[1]), "=r"(r[2]), "=r"(r[3]) : "r"(addr));
}
__device__ __forceinline__ void ldsm4t(uint32_t* r, uint32_t addr) {
    asm volatile("ldmatrix.sync.aligned.m8n8.x4.trans.shared.b16 {%0,%1,%2,%3}, [%4];"
                 : "=r"(r[0]), "=r"(r[1]), "=r"(r[2]), "=r"(r[3]) : "r"(addr));
}
__device__ __forceinline__ void mma8(float* c, const uint32_t* a, uint32_t b0, uint32_t b1) {
    asm volatile("mma.sync.aligned.m16n8k8.row.col.f32.tf32.tf32.f32 "
                 "{%0,%1,%2,%3}, {%4,%5,%6,%7}, {%8,%9}, {%0,%1,%2,%3};"
                 : "+f"(c[0]), "+f"(c[1]), "+f"(c[2]), "+f"(c[3])
                 : "r"(a[0]), "r"(a[1]), "r"(a[2]), "r"(a[3]), "r"(b0), "r"(b1));
}
__device__ __forceinline__ void mma16(float* c, const uint32_t* a, uint32_t b0, uint32_t b1) {
    asm volatile("mma.sync.aligned.m16n8k16.row.col.f32.f16.f16.f32 "
                 "{%0,%1,%2,%3}, {%4,%5,%6,%7}, {%8,%9}, {%0,%1,%2,%3};"
                 : "+f"(c[0]), "+f"(c[1]), "+f"(c[2]), "+f"(c[3])
                 : "r"(a[0]), "r"(a[1]), "r"(a[2]), "r"(a[3]), "r"(b0), "r"(b1));
}
__device__ __forceinline__ void cpa16(uint32_t dst, const void* src) {
    asm volatile("cp.async.cg.shared.global [%0], [%1], 16;" :: "r"(dst), "l"(src) : "memory");
}
#define CPA_COMMIT() asm volatile("cp.async.commit_group;" ::: "memory")
#define CPA_WAIT1()  asm volatile("cp.async.wait_group 1;" ::: "memory")

__global__ __launch_bounds__(256, 2)
void bs_attn_mma(const float* __restrict__ qg_,
                 const float* __restrict__ kg_,
                 const float* __restrict__ vg_,
                 float* __restrict__ out)
{
    const int pr  = 31 - (int)blockIdx.x;     /* heavy pairs first */
    const int qlo = pr << 1;                  /* CTA covers q-blocks qlo, qlo+1 */
    const int h   = (int)blockIdx.y;

    extern __shared__ char sb[];
    const uint32_t smu = smem_u32(sb);
    const int tid  = (int)threadIdx.x;
    const int lane = tid & 31;
    const int w    = tid >> 5;                /* 8 warps, warp owns rows 16w..16w+15 */
    const int g    = lane >> 2;
    const int t    = lane & 3;
    const int l16  = lane & 15;
    const int lh   = lane >> 4;

    /* loader mapping: thread -> (token row jq, d-group dg of 16 floats) */
    const int jq = tid & 63;
    const int dg = (tid >> 6) << 4;           /* 0,16,32,48 */

    /* ---- stage Q (128 rows, tf32 rna) through K0+K1 (fp32 tiles) ---- */
    #pragma unroll
    for (int e = 0; e < 8; ++e) {
        const int idx = (e << 8) + tid;
        const int row = idx >> 4, d4 = idx & 15;
        const float* qgb = qg_ + (size_t)(qlo * 64 + row) * HD + h * 64 + (d4 << 2);
        float4 v = *reinterpret_cast<const float4*>(qgb);
        uint4 u = make_uint4(tf32r(v.x), tf32r(v.y), tf32r(v.z), tf32r(v.w));
        const int base = (row < 64) ? SM_K0 : SM_K1;
        *reinterpret_cast<uint4*>(sb + base + (((row & 63) * LD) + (d4 << 2)) * 4) = u;
    }
    __syncthreads();

    uint32_t qa[32];
    {
        const int qrow = (16 * w) & 63;
        const uint32_t rbase = smu + ((w < 4) ? SM_K0 : SM_K1)
                             + (uint32_t)((qrow + l16) * LD) * 4;
        #pragma unroll
        for (int s = 0; s < 8; ++s)
            ldsm4(qa + 4 * s, rbase + (uint32_t)(2 * s + lh) * 16);
    }
    __syncthreads();   /* qa loaded; K buffers free for cp.async */

    /* ---- k-block enumeration for the pair ---- */
    const int rv  = (7 - h) & 7;
    const int nv  = (qlo - 8 >= rv) ? (((qlo - 8 - rv) >> 3) + 1) : 0;
    const int j0  = (qlo - 7 > 0) ? (qlo - 7) : 0;
    const int nb  = nv + (qlo + 2 - j0);

    const int qbw = qlo + (w >> 2);           /* warps 0-3: qlo, 4-7: qlo+1 */
    const int rowj_off = (lh << 3) + (lane & 7);
    const int grp_half = (lane >> 3) & 1;

    /* prologue: cp.async K(first block) into buffer 0 */
    {
        const int kb0 = (0 < nv) ? rv : j0;
        const float* kgb = kg_ + (size_t)(kb0 * 64 + jq) * HD + h * 64 + dg;
        const uint32_t kdst = smu + SM_K0 + (uint32_t)((jq * LD + dg) * 4);
        #pragma unroll
        for (int e = 0; e < 4; ++e)
            cpa16(kdst + (e << 4), kgb + (e << 2));
        CPA_COMMIT();
    }

    float oacc[8][4];
    #pragma unroll
    for (int nt = 0; nt < 8; ++nt)
        #pragma unroll
        for (int c = 0; c < 4; ++c) oacc[nt][c] = 0.0f;
    float lacc[4] = {0.0f, 0.0f, 0.0f, 0.0f};

    for (int it = 0; it < nb; ++it) {
        const int kb  = (it < nv) ? (rv + (it << 3)) : (j0 + it - nv);
        const int itn = (it + 1 < nb) ? (it + 1) : it;
        const int kbn = (itn < nv) ? (rv + (itn << 3)) : (j0 + itn - nv);

        /* V prefetch into registers */
        const float* vgb = vg_ + (size_t)(kb * 64 + jq) * HD + h * 64 + dg;
        float4 vr[4];
        #pragma unroll
        for (int e = 0; e < 4; ++e)
            vr[e] = *reinterpret_cast<const float4*>(vgb + (e << 2));

        __syncthreads();   /* prev iter readers of K(it-1)/V done */

        /* cp.async next K into the other buffer */
        {
            const float* kgb = kg_ + (size_t)(kbn * 64 + jq) * HD + h * 64 + dg;
            const uint32_t kdst = smu + (((it + 1) & 1) ? SM_K1 : SM_K0)
                                      + (uint32_t)((jq * LD + dg) * 4);
            #pragma unroll
            for (int e = 0; e < 4; ++e)
                cpa16(kdst + (e << 4), kgb + (e << 2));
            CPA_COMMIT();
        }

        /* V natural fp16 store: sV[j][d], 16 halfs = 2 STS.128 */
        {
            uint4 u0, u1;
            u0.x = f16x2(vr[0].y, vr[0].x); u0.y = f16x2(vr[0].w, vr[0].z);
            u0.z = f16x2(vr[1].y, vr[1].x); u0.w = f16x2(vr[1].w, vr[1].z);
            u1.x = f16x2(vr[2].y, vr[2].x); u1.y = f16x2(vr[2].w, vr[2].z);
            u1.z = f16x2(vr[3].y, vr[3].x); u1.w = f16x2(vr[3].w, vr[3].z);
            char* vdst = sb + SM_V + jq * LDHB + dg * 2;
            *reinterpret_cast<uint4*>(vdst)      = u0;
            *reinterpret_cast<uint4*>(vdst + 16) = u1;
        }
        CPA_WAIT1();       /* K(it) resident */
        __syncthreads();   /* K(it) + V(it) visible */

        const uint32_t kbase = smu + ((it & 1) ? SM_K1 : SM_K0);

        /* warp-uniform predicates for this warp's q-block */
        const bool alw  = (kb <= qbw) && (((qbw - kb) < 8) || ((kb & 7) == rv));
        const bool diag = (kb == qbw);

        if (alw) {
            float acc[8][4];
            #pragma unroll
            for (int nt = 0; nt < 8; ++nt)
                #pragma unroll
                for (int c = 0; c < 4; ++c) acc[nt][c] = 0.0f;

            /* GEMM1 (tf32): S = Q @ K^T (16 rows x 64 cols) */
            #pragma unroll
            for (int s = 0; s < 8; ++s) {
                uint32_t kb4[16];
                #pragma unroll
                for (int ntp = 0; ntp < 4; ++ntp)
                    ldsm4(kb4 + 4 * ntp,
                          kbase + (uint32_t)((16 * ntp + rowj_off) * LD) * 4
                                + (uint32_t)(2 * s + grp_half) * 16);
                #pragma unroll
                for (int nt = 0; nt < 8; ++nt)
                    mma8(acc[nt], qa + 4 * s, kb4[2 * nt], kb4[2 * nt + 1]);
            }

            /* softmax (no max subtraction; scores bounded) + fp16 P store */
            const int r0  = 16 * w + g;
            const int ri0 = r0 & 63;
            #pragma unroll
            for (int nt = 0; nt < 8; ++nt) {
                const int col = 8 * nt + 2 * t;
                float p0 = ex2a(acc[nt][0] * COEF);
                float p1 = ex2a(acc[nt][1] * COEF);
                float p2 = ex2a(acc[nt][2] * COEF);
                float p3 = ex2a(acc[nt][3] * COEF);
                if (diag) {
                    if (col     > ri0)     p0 = 0.0f;
                    if (col + 1 > ri0)     p1 = 0.0f;
                    if (col     > ri0 + 8) p2 = 0.0f;
                    if (col + 1 > ri0 + 8) p3 = 0.0f;
                }
                *reinterpret_cast<uint32_t*>(sb + SM_P + r0 * LDHB + col * 2) =
                    f16x2(p1, p0);
                *reinterpret_cast<uint32_t*>(sb + SM_P + (r0 + 8) * LDHB + col * 2) =
                    f16x2(p3, p2);
            }
            __syncwarp();  /* P rows are warp-private */

            /* GEMM2 (fp16): O += P @ V ; lsum via ones-B MMA */
            #pragma unroll
            for (int ks = 0; ks < 4; ++ks) {
                uint32_t pa[4];
                ldsm4(pa, smu + SM_P + (uint32_t)((16 * w + l16) * LDHB)
                                     + (uint32_t)(ks * 32 + lh * 16));
                mma16(lacc, pa, ONESH, ONESH);
                uint32_t vb[16];
                #pragma unroll
                for (int dp = 0; dp < 4; ++dp)
                    ldsm4t(vb + 4 * dp,
                           smu + SM_V + (uint32_t)((ks * 16 + l16) * LDHB)
                                      + (uint32_t)(dp * 32 + lh * 16));
                #pragma unroll
                for (int nt = 0; nt < 8; ++nt) {
                    const int bi = 4 * (nt >> 1) + 2 * (nt & 1);
                    mma16(oacc[nt], pa, vb[bi], vb[bi + 1]);
                }
            }
        }
    }

    /* ---- finalize: lsum already in lacc (all n-cols identical) ---- */
    const float inv0 = 1.0f / lacc[0];
    const float inv1 = 1.0f / lacc[2];

    const int r0 = 16 * w + g;
    float* ob0 = out + (size_t)(qlo * 64 + r0) * HD + h * 64;
    float* ob1 = ob0 + (size_t)8 * HD;
    #pragma unroll
    for (int nt = 0; nt < 8; ++nt) {
        const int col = 8 * nt + 2 * t;
        *reinterpret_cast<float2*>(ob0 + col) =
            make_float2(oacc[nt][0] * inv0, oacc[nt][1] * inv0);
        *reinterpret_cast<float2*>(ob1 + col) =
            make_float2(oacc[nt][2] * inv1, oacc[nt][3] * inv1);
    }
}

extern "C" void kernel_launch(void* const* d_in, const int* in_sizes, int n_in,
                              void* d_out, int out_size)
{
    const float* q = (const float*)d_in[0];
    const float* k = (const float*)d_in[1];
    const float* v = (const float*)d_in[2];
    /* d_in[3] = cu_seqlens_k, fixed [0, 4096] — unused */
    float* out = (float*)d_out;

    cudaFuncSetAttribute(bs_attn_mma,
                         cudaFuncAttributeMaxDynamicSharedMemorySize, SMEM_BYTES);
    dim3 grid(32, NHEADS);
    bs_attn_mma<<<grid, 256, SMEM_BYTES>>>(q, k, v, out);
}

// round 12
// speedup vs baseline: 3.9932x; 1.4916x over previous
#include <cuda_runtime.h>
#include <cuda_fp16.h>
#include <cstdint>
#include <math.h>

#define NHEADS 16
#define HD     1024            /* elements per token row (16 heads x 64) */
#define LDHB   144             /* fp16 SMEM row stride in BYTES (72 halfs) */
#define COEF   0.18033688011112042f   /* log2(e)/8 */
#define ONESH  0x3C003C00u     /* f16x2 (1.0, 1.0) */

/* SMEM: double-buffered fp16 K and V tiles (64 rows x 128B, padded to 144B).
   Q (128 rows fp16) stages through K0+V0 in the prologue. */
#define SM_K0  0
#define SM_V0  9216
#define SM_K1  18432
#define SM_V1  27648
#define SMEM_BYTES 36864

/* fp16 copies of K and V, produced once per launch by cvt_kv */
__device__ __half KH[4096 * 1024];
__device__ __half VH[4096 * 1024];

__device__ __forceinline__ uint32_t smem_u32(const void* p) {
    uint32_t a;
    asm("{ .reg .u64 t; cvta.to.shared.u64 t, %1; cvt.u32.u64 %0, t; }" : "=r"(a) : "l"(p));
    return a;
}
__device__ __forceinline__ uint32_t f16x2(float hi, float lo) {
    uint32_t r; asm("cvt.rn.f16x2.f32 %0, %1, %2;" : "=r"(r) : "f"(hi), "f"(lo)); return r;
}
__device__ __forceinline__ float ex2a(float x) {
    float r; asm("ex2.approx.f32 %0, %1;" : "=f"(r) : "f"(x)); return r;
}
__device__ __forceinline__ void ldsm4(uint32_t* r, uint32_t addr) {
    asm volatile("ldmatrix.sync.aligned.m8n8.x4.shared.b16 {%0,%1,%2,%3}, [%4];"
                 : "=r"(r[0]), "=r"(r[1]), "=r"(r[2]), "=r"(r[3]) : "r"(addr));
}
__device__ __forceinline__ void ldsm4t(uint32_t* r, uint32_t addr) {
    asm volatile("ldmatrix.sync.aligned.m8n8.x4.trans.shared.b16 {%0,%1,%2,%3}, [%4];"
                 : "=r"(r[0]), "=r"(r[1]), "=r"(r[2]), "=r"(r[3]) : "r"(addr));
}
__device__ __forceinline__ void mma16(float* c, const uint32_t* a, uint32_t b0, uint32_t b1) {
    asm volatile("mma.sync.aligned.m16n8k16.row.col.f32.f16.f16.f32 "
                 "{%0,%1,%2,%3}, {%4,%5,%6,%7}, {%8,%9}, {%0,%1,%2,%3};"
                 : "+f"(c[0]), "+f"(c[1]), "+f"(c[2]), "+f"(c[3])
                 : "r"(a[0]), "r"(a[1]), "r"(a[2]), "r"(a[3]), "r"(b0), "r"(b1));
}
__device__ __forceinline__ void cpa16(uint32_t dst, const void* src) {
    asm volatile("cp.async.cg.shared.global [%0], [%1], 16;" :: "r"(dst), "l"(src) : "memory");
}
#define CPA_COMMIT() asm volatile("cp.async.commit_group;" ::: "memory")
#define CPA_WAIT1()  asm volatile("cp.async.wait_group 1;" ::: "memory")

/* ---- prepass: fp32 -> fp16 copies of K and V ---- */
__global__ __launch_bounds__(256)
void cvt_kv(const float* __restrict__ kg, const float* __restrict__ vg)
{
    const size_t i = (size_t)blockIdx.x * blockDim.x + threadIdx.x;  /* float4 units */
    const float* src = blockIdx.y ? vg : kg;
    __half2* dst = reinterpret_cast<__half2*>((blockIdx.y ? VH : KH) + i * 4);
    float4 v = *reinterpret_cast<const float4*>(src + i * 4);
    dst[0] = __floats2half2_rn(v.x, v.y);
    dst[1] = __floats2half2_rn(v.z, v.w);
}

__global__ __launch_bounds__(256, 2)
void bs_attn_mma(const float* __restrict__ qg_, float* __restrict__ out)
{
    const int pr  = 31 - (int)blockIdx.x;     /* heavy pairs first */
    const int qlo = pr << 1;                  /* CTA covers q-blocks qlo, qlo+1 */
    const int h   = (int)blockIdx.y;

    extern __shared__ char sb[];
    const uint32_t smu = smem_u32(sb);
    const int tid  = (int)threadIdx.x;
    const int lane = tid & 31;
    const int w    = tid >> 5;                /* 8 warps, warp owns rows 16w..16w+15 */
    const int g    = lane >> 2;
    const int t    = lane & 3;
    const int l16  = lane & 15;
    const int lh   = lane >> 4;

    /* loader mapping: thread -> (token row jq, half-group dgh of 16 halfs) */
    const int jq  = tid & 63;
    const int dgh = (tid >> 6) << 4;          /* 0,16,32,48 halfs */

    /* ---- stage Q (128 rows, fp16 rn) into SMEM rows 0..127 ---- */
    #pragma unroll
    for (int e = 0; e < 8; ++e) {
        const int idx = (e << 8) + tid;       /* 2048 float4 groups */
        const int row = idx >> 4, d4 = idx & 15;
        float4 v = *reinterpret_cast<const float4*>(
            qg_ + (size_t)(qlo * 64 + row) * HD + h * 64 + (d4 << 2));
        uint2 u;
        u.x = f16x2(v.y, v.x);
        u.y = f16x2(v.w, v.z);
        *reinterpret_cast<uint2*>(sb + row * LDHB + (d4 << 3)) = u;
    }
    __syncthreads();

    uint32_t qa[16];                          /* fp16 A-frags for 4 k16-steps */
    {
        const uint32_t rbase = smu + (uint32_t)((16 * w + l16) * LDHB) + (uint32_t)(lh * 16);
        #pragma unroll
        for (int ks = 0; ks < 4; ++ks)
            ldsm4(qa + 4 * ks, rbase + ks * 32);
    }
    __syncthreads();   /* qa loaded; staging area free for cp.async */

    /* ---- k-block enumeration for the pair ---- */
    const int rv  = (7 - h) & 7;
    const int nv  = (qlo - 8 >= rv) ? (((qlo - 8 - rv) >> 3) + 1) : 0;
    const int j0  = (qlo - 7 > 0) ? (qlo - 7) : 0;
    const int nb  = nv + (qlo + 2 - j0);

    const int qbw = qlo + (w >> 2);           /* warps 0-3: qlo, 4-7: qlo+1 */
    const int rowj_off = (lh << 3) + (lane & 7);
    const int grp_half = (lane >> 3) & 1;

    /* prologue: cp.async K(0),V(0) into buffer 0 */
    {
        const int kb0 = (0 < nv) ? rv : j0;
        const __half* ksrc = KH + (size_t)(kb0 * 64 + jq) * HD + h * 64 + dgh;
        const __half* vsrc = VH + (size_t)(kb0 * 64 + jq) * HD + h * 64 + dgh;
        const uint32_t kd = smu + SM_K0 + (uint32_t)(jq * LDHB + dgh * 2);
        const uint32_t vd = smu + SM_V0 + (uint32_t)(jq * LDHB + dgh * 2);
        cpa16(kd, ksrc);      cpa16(kd + 16, ksrc + 8);
        cpa16(vd, vsrc);      cpa16(vd + 16, vsrc + 8);
        CPA_COMMIT();
    }

    float oacc[8][4];
    #pragma unroll
    for (int nt = 0; nt < 8; ++nt)
        #pragma unroll
        for (int c = 0; c < 4; ++c) oacc[nt][c] = 0.0f;
    float lacc[4] = {0.0f, 0.0f, 0.0f, 0.0f};

    for (int it = 0; it < nb; ++it) {
        const int kb  = (it < nv) ? (rv + (it << 3)) : (j0 + it - nv);
        const int itn = (it + 1 < nb) ? (it + 1) : it;
        const int kbn = (itn < nv) ? (rv + (itn << 3)) : (j0 + itn - nv);

        __syncthreads();   /* readers of buffer[(it+1)&1] (iter it-1) done */

        /* cp.async next K,V into the other buffer */
        {
            const __half* ksrc = KH + (size_t)(kbn * 64 + jq) * HD + h * 64 + dgh;
            const __half* vsrc = VH + (size_t)(kbn * 64 + jq) * HD + h * 64 + dgh;
            const uint32_t kd = smu + (((it + 1) & 1) ? SM_K1 : SM_K0)
                              + (uint32_t)(jq * LDHB + dgh * 2);
            const uint32_t vd = smu + (((it + 1) & 1) ? SM_V1 : SM_V0)
                              + (uint32_t)(jq * LDHB + dgh * 2);
            cpa16(kd, ksrc);      cpa16(kd + 16, ksrc + 8);
            cpa16(vd, vsrc);      cpa16(vd + 16, vsrc + 8);
            CPA_COMMIT();
        }
        CPA_WAIT1();       /* group(it) complete */
        __syncthreads();   /* K(it),V(it) visible to all threads */

        const uint32_t kbase = smu + ((it & 1) ? SM_K1 : SM_K0);
        const uint32_t vbase = smu + ((it & 1) ? SM_V1 : SM_V0);

        /* warp-uniform predicates for this warp's q-block */
        const bool alw  = (kb <= qbw) && (((qbw - kb) < 8) || ((kb & 7) == rv));
        const bool diag = (kb == qbw);

        if (alw) {
            float acc[8][4];
            #pragma unroll
            for (int nt = 0; nt < 8; ++nt)
                #pragma unroll
                for (int c = 0; c < 4; ++c) acc[nt][c] = 0.0f;

            /* GEMM1 (fp16): S = Q @ K^T (16 rows x 64 cols) */
            #pragma unroll
            for (int ks = 0; ks < 4; ++ks) {
                uint32_t kb4[16];
                #pragma unroll
                for (int ntp = 0; ntp < 4; ++ntp)
                    ldsm4(kb4 + 4 * ntp,
                          kbase + (uint32_t)((16 * ntp + rowj_off) * LDHB)
                                + (uint32_t)(ks * 32 + grp_half * 16));
                #pragma unroll
                for (int nt = 0; nt < 8; ++nt) {
                    const int bi = 4 * (nt >> 1) + 2 * (nt & 1);
                    mma16(acc[nt], qa + 4 * ks, kb4[bi], kb4[bi + 1]);
                }
            }

            /* softmax (no max subtraction; scores bounded) -> packed fp16 A-frags */
            const int r0  = 16 * w + g;
            const int ri0 = r0 & 63;
            uint32_t pp[16];
            #pragma unroll
            for (int nt = 0; nt < 8; ++nt) {
                const int col = 8 * nt + 2 * t;
                float p0 = ex2a(acc[nt][0] * COEF);
                float p1 = ex2a(acc[nt][1] * COEF);
                float p2 = ex2a(acc[nt][2] * COEF);
                float p3 = ex2a(acc[nt][3] * COEF);
                if (diag) {
                    if (col     > ri0)     p0 = 0.0f;
                    if (col + 1 > ri0)     p1 = 0.0f;
                    if (col     > ri0 + 8) p2 = 0.0f;
                    if (col + 1 > ri0 + 8) p3 = 0.0f;
                }
                pp[2 * nt]     = f16x2(p1, p0);   /* row g,   k-pair */
                pp[2 * nt + 1] = f16x2(p3, p2);   /* row g+8, k-pair */
            }

            /* GEMM2 (fp16): O += P @ V with P in registers; lsum via ones-B */
            #pragma unroll
            for (int ks = 0; ks < 4; ++ks) {
                const uint32_t* pa = pp + 4 * ks;   /* A-frag for k16 step ks */
                mma16(lacc, pa, ONESH, ONESH);
                uint32_t vb[16];
                #pragma unroll
                for (int dp = 0; dp < 4; ++dp)
                    ldsm4t(vb + 4 * dp,
                           vbase + (uint32_t)((ks * 16 + l16) * LDHB)
                                 + (uint32_t)(dp * 32 + lh * 16));
                #pragma unroll
                for (int nt = 0; nt < 8; ++nt) {
                    const int bi = 4 * (nt >> 1) + 2 * (nt & 1);
                    mma16(oacc[nt], pa, vb[bi], vb[bi + 1]);
                }
            }
        }
    }

    /* ---- finalize: lsum in lacc (all n-cols identical) ---- */
    const float inv0 = 1.0f / lacc[0];
    const float inv1 = 1.0f / lacc[2];

    const int r0 = 16 * w + g;
    float* ob0 = out + (size_t)(qlo * 64 + r0) * HD + h * 64;
    float* ob1 = ob0 + (size_t)8 * HD;
    #pragma unroll
    for (int nt = 0; nt < 8; ++nt) {
        const int col = 8 * nt + 2 * t;
        *reinterpret_cast<float2*>(ob0 + col) =
            make_float2(oacc[nt][0] * inv0, oacc[nt][1] * inv0);
        *reinterpret_cast<float2*>(ob1 + col) =
            make_float2(oacc[nt][2] * inv1, oacc[nt][3] * inv1);
    }
}

extern "C" void kernel_launch(void* const* d_in, const int* in_sizes, int n_in,
                              void* d_out, int out_size)
{
    const float* q = (const float*)d_in[0];
    const float* k = (const float*)d_in[1];
    const float* v = (const float*)d_in[2];
    /* d_in[3] = cu_seqlens_k, fixed [0, 4096] — unused */
    float* out = (float*)d_out;

    /* prepass: K,V -> fp16 (4096*1024/4 float4s per tensor) */
    dim3 cgrid(4096, 2);
    cvt_kv<<<cgrid, 256>>>(k, v);

    cudaFuncSetAttribute(bs_attn_mma,
                         cudaFuncAttributeMaxDynamicSharedMemorySize, SMEM_BYTES);
    dim3 grid(32, NHEADS);
    bs_attn_mma<<<grid, 256, SMEM_BYTES>>>(q, out);
}

// round 13
// speedup vs baseline: 4.5637x; 1.1429x over previous
#include <cuda_runtime.h>
#include <cuda_fp16.h>
#include <cstdint>
#include <math.h>

#define NHEADS 16
#define HD     1024            /* elements per token row (16 heads x 64) */
#define LDHB   144             /* fp16 SMEM row stride in BYTES (72 halfs) */
#define COEF   0.18033688011112042f   /* log2(e)/8 */
#define ONESH  0x3C003C00u     /* f16x2 (1.0, 1.0) */

/* SMEM: 3-stage pipeline of fp16 K+V tiles (stage = 9216 K + 9216 V).
   Q (128 rows fp16) stages through stage 0 in the prologue. */
#define STAGE_B 18432
#define SMEM_BYTES (3 * STAGE_B)   /* 55296 B */

/* fp16 copies of K and V, produced once per launch by cvt_kv */
__device__ __half KH[4096 * 1024];
__device__ __half VH[4096 * 1024];

__device__ __forceinline__ uint32_t smem_u32(const void* p) {
    uint32_t a;
    asm("{ .reg .u64 t; cvta.to.shared.u64 t, %1; cvt.u32.u64 %0, t; }" : "=r"(a) : "l"(p));
    return a;
}
__device__ __forceinline__ uint32_t f16x2(float hi, float lo) {
    uint32_t r; asm("cvt.rn.f16x2.f32 %0, %1, %2;" : "=r"(r) : "f"(hi), "f"(lo)); return r;
}
__device__ __forceinline__ float ex2a(float x) {
    float r; asm("ex2.approx.f32 %0, %1;" : "=f"(r) : "f"(x)); return r;
}
__device__ __forceinline__ void ldsm4(uint32_t* r, uint32_t addr) {
    asm volatile("ldmatrix.sync.aligned.m8n8.x4.shared.b16 {%0,%1,%2,%3}, [%4];"
                 : "=r"(r[0]), "=r"(r[1]), "=r"(r[2]), "=r"(r[3]) : "r"(addr));
}
__device__ __forceinline__ void ldsm4t(uint32_t* r, uint32_t addr) {
    asm volatile("ldmatrix.sync.aligned.m8n8.x4.trans.shared.b16 {%0,%1,%2,%3}, [%4];"
                 : "=r"(r[0]), "=r"(r[1]), "=r"(r[2]), "=r"(r[3]) : "r"(addr));
}
__device__ __forceinline__ void mma16(float* c, const uint32_t* a, uint32_t b0, uint32_t b1) {
    asm volatile("mma.sync.aligned.m16n8k16.row.col.f32.f16.f16.f32 "
                 "{%0,%1,%2,%3}, {%4,%5,%6,%7}, {%8,%9}, {%0,%1,%2,%3};"
                 : "+f"(c[0]), "+f"(c[1]), "+f"(c[2]), "+f"(c[3])
                 : "r"(a[0]), "r"(a[1]), "r"(a[2]), "r"(a[3]), "r"(b0), "r"(b1));
}
__device__ __forceinline__ void cpa16(uint32_t dst, const void* src) {
    asm volatile("cp.async.cg.shared.global [%0], [%1], 16;" :: "r"(dst), "l"(src) : "memory");
}
#define CPA_COMMIT() asm volatile("cp.async.commit_group;" ::: "memory")
#define CPA_WAIT1()  asm volatile("cp.async.wait_group 1;" ::: "memory")

/* ---- prepass: fp32 -> fp16 copies of K and V ---- */
__global__ __launch_bounds__(256)
void cvt_kv(const float* __restrict__ kg, const float* __restrict__ vg)
{
    const size_t i = (size_t)blockIdx.x * blockDim.x + threadIdx.x;  /* float4 units */
    const float* src = blockIdx.y ? vg : kg;
    __half2* dst = reinterpret_cast<__half2*>((blockIdx.y ? VH : KH) + i * 4);
    float4 v = *reinterpret_cast<const float4*>(src + i * 4);
    dst[0] = __floats2half2_rn(v.x, v.y);
    dst[1] = __floats2half2_rn(v.z, v.w);
}

__global__ __launch_bounds__(256, 2)
void bs_attn_mma(const float* __restrict__ qg_, float* __restrict__ out)
{
    /* global LPT order: all heads' heaviest pairs first */
    const int bid = (int)blockIdx.x;
    const int pr  = 31 - (bid >> 4);
    const int h   = bid & 15;
    const int qlo = pr << 1;                  /* CTA covers q-blocks qlo, qlo+1 */

    extern __shared__ char sb[];
    const uint32_t smu = smem_u32(sb);
    const int tid  = (int)threadIdx.x;
    const int lane = tid & 31;
    const int w    = tid >> 5;                /* 8 warps, warp owns rows 16w..16w+15 */
    const int g    = lane >> 2;
    const int t    = lane & 3;
    const int l16  = lane & 15;
    const int lh   = lane >> 4;

    /* loader mapping: thread -> (token row jq, half-group dgh of 16 halfs) */
    const int jq  = tid & 63;
    const int dgh = (tid >> 6) << 4;          /* 0,16,32,48 halfs */

    /* ---- stage Q (128 rows, fp16 rn) into stage-0 area ---- */
    #pragma unroll
    for (int e = 0; e < 8; ++e) {
        const int idx = (e << 8) + tid;       /* 2048 float4 groups */
        const int row = idx >> 4, d4 = idx & 15;
        float4 v = *reinterpret_cast<const float4*>(
            qg_ + (size_t)(qlo * 64 + row) * HD + h * 64 + (d4 << 2));
        uint2 u;
        u.x = f16x2(v.y, v.x);
        u.y = f16x2(v.w, v.z);
        *reinterpret_cast<uint2*>(sb + row * LDHB + (d4 << 3)) = u;
    }
    __syncthreads();

    uint32_t qa[16];                          /* fp16 A-frags for 4 k16-steps */
    {
        const uint32_t rbase = smu + (uint32_t)((16 * w + l16) * LDHB) + (uint32_t)(lh * 16);
        #pragma unroll
        for (int ks = 0; ks < 4; ++ks)
            ldsm4(qa + 4 * ks, rbase + ks * 32);
    }
    __syncthreads();   /* qa loaded; staging area free for cp.async */

    /* ---- k-block enumeration for the pair ---- */
    const int rv  = (7 - h) & 7;
    const int nv  = (qlo - 8 >= rv) ? (((qlo - 8 - rv) >> 3) + 1) : 0;
    const int j0  = (qlo - 7 > 0) ? (qlo - 7) : 0;
    const int nb  = nv + (qlo + 2 - j0);      /* >= 2 always */

    const int qbw = qlo + (w >> 2);           /* warps 0-3: qlo, 4-7: qlo+1 */
    const int rowj_off = (lh << 3) + (lane & 7);
    const int grp_half = (lane >> 3) & 1;

    /* k-block id for iteration i */
    #define KB_OF(i) (((i) < nv) ? (rv + ((i) << 3)) : (j0 + (i) - nv))
    /* cp.async one K+V stage (this thread's 2x32B slices) */
    #define LOAD_STAGE(i, st) do {                                                  \
        const int _kb = KB_OF(i);                                                   \
        const __half* _ks = KH + (size_t)(_kb * 64 + jq) * HD + h * 64 + dgh;       \
        const __half* _vs = VH + (size_t)(_kb * 64 + jq) * HD + h * 64 + dgh;       \
        const uint32_t _kd = smu + (uint32_t)((st) * STAGE_B)                       \
                           + (uint32_t)(jq * LDHB + dgh * 2);                       \
        cpa16(_kd, _ks);          cpa16(_kd + 16, _ks + 8);                         \
        cpa16(_kd + 9216, _vs);   cpa16(_kd + 9216 + 16, _vs + 8);                  \
        CPA_COMMIT();                                                               \
    } while (0)

    /* prologue: fill stages 0 and 1 */
    LOAD_STAGE(0, 0);
    {
        const int i1 = (1 < nb) ? 1 : 0;
        LOAD_STAGE(i1, 1);
    }

    float oacc[8][4];
    #pragma unroll
    for (int nt = 0; nt < 8; ++nt)
        #pragma unroll
        for (int c = 0; c < 4; ++c) oacc[nt][c] = 0.0f;
    float lacc[4] = {0.0f, 0.0f, 0.0f, 0.0f};

    int stage = 0;       /* stage holding block(it) */
    for (int it = 0; it < nb; ++it) {
        const int kb = KB_OF(it);

        CPA_WAIT1();       /* group(it) (issued 2 iters ago) complete locally */
        __syncthreads();   /* globally visible + compute(it-1) finished everywhere */

        /* issue load(it+2) into the stage freed by compute(it-1) */
        {
            const int i2 = (it + 2 < nb) ? (it + 2) : (nb - 1);
            const int st2 = (stage + 2 >= 3) ? (stage - 1) : (stage + 2);
            LOAD_STAGE(i2, st2);
        }

        const uint32_t kbase = smu + (uint32_t)(stage * STAGE_B);
        const uint32_t vbase = kbase + 9216;

        /* warp-uniform predicates for this warp's q-block */
        const bool alw  = (kb <= qbw) && (((qbw - kb) < 8) || ((kb & 7) == rv));
        const bool diag = (kb == qbw);

        if (alw) {
            float acc[8][4];
            #pragma unroll
            for (int nt = 0; nt < 8; ++nt)
                #pragma unroll
                for (int c = 0; c < 4; ++c) acc[nt][c] = 0.0f;

            /* GEMM1 (fp16): S = Q @ K^T (16 rows x 64 cols) */
            #pragma unroll
            for (int ks = 0; ks < 4; ++ks) {
                uint32_t kb4[16];
                #pragma unroll
                for (int ntp = 0; ntp < 4; ++ntp)
                    ldsm4(kb4 + 4 * ntp,
                          kbase + (uint32_t)((16 * ntp + rowj_off) * LDHB)
                                + (uint32_t)(ks * 32 + grp_half * 16));
                #pragma unroll
                for (int nt = 0; nt < 8; ++nt) {
                    const int bi = 4 * (nt >> 1) + 2 * (nt & 1);
                    mma16(acc[nt], qa + 4 * ks, kb4[bi], kb4[bi + 1]);
                }
            }

            /* softmax (no max subtraction; scores bounded) -> packed fp16 A-frags */
            const int r0  = 16 * w + g;
            const int ri0 = r0 & 63;
            uint32_t pp[16];
            #pragma unroll
            for (int nt = 0; nt < 8; ++nt) {
                const int col = 8 * nt + 2 * t;
                float p0 = ex2a(acc[nt][0] * COEF);
                float p1 = ex2a(acc[nt][1] * COEF);
                float p2 = ex2a(acc[nt][2] * COEF);
                float p3 = ex2a(acc[nt][3] * COEF);
                if (diag) {
                    if (col     > ri0)     p0 = 0.0f;
                    if (col + 1 > ri0)     p1 = 0.0f;
                    if (col     > ri0 + 8) p2 = 0.0f;
                    if (col + 1 > ri0 + 8) p3 = 0.0f;
                }
                pp[2 * nt]     = f16x2(p1, p0);   /* row g,   k-pair */
                pp[2 * nt + 1] = f16x2(p3, p2);   /* row g+8, k-pair */
            }

            /* GEMM2 (fp16): O += P @ V with P in registers; lsum via ones-B */
            #pragma unroll
            for (int ks = 0; ks < 4; ++ks) {
                const uint32_t* pa = pp + 4 * ks;   /* A-frag for k16 step ks */
                mma16(lacc, pa, ONESH, ONESH);
                uint32_t vb[16];
                #pragma unroll
                for (int dp = 0; dp < 4; ++dp)
                    ldsm4t(vb + 4 * dp,
                           vbase + (uint32_t)((ks * 16 + l16) * LDHB)
                                 + (uint32_t)(dp * 32 + lh * 16));
                #pragma unroll
                for (int nt = 0; nt < 8; ++nt) {
                    const int bi = 4 * (nt >> 1) + 2 * (nt & 1);
                    mma16(oacc[nt], pa, vb[bi], vb[bi + 1]);
                }
            }
        }

        stage = (stage + 1 >= 3) ? 0 : (stage + 1);
    }

    /* ---- finalize: lsum in lacc (all n-cols identical) ---- */
    const float inv0 = 1.0f / lacc[0];
    const float inv1 = 1.0f / lacc[2];

    const int r0 = 16 * w + g;
    float* ob0 = out + (size_t)(qlo * 64 + r0) * HD + h * 64;
    float* ob1 = ob0 + (size_t)8 * HD;
    #pragma unroll
    for (int nt = 0; nt < 8; ++nt) {
        const int col = 8 * nt + 2 * t;
        *reinterpret_cast<float2*>(ob0 + col) =
            make_float2(oacc[nt][0] * inv0, oacc[nt][1] * inv0);
        *reinterpret_cast<float2*>(ob1 + col) =
            make_float2(oacc[nt][2] * inv1, oacc[nt][3] * inv1);
    }
}

extern "C" void kernel_launch(void* const* d_in, const int* in_sizes, int n_in,
                              void* d_out, int out_size)
{
    const float* q = (const float*)d_in[0];
    const float* k = (const float*)d_in[1];
    const float* v = (const float*)d_in[2];
    /* d_in[3] = cu_seqlens_k, fixed [0, 4096] — unused */
    float* out = (float*)d_out;

    /* prepass: K,V -> fp16 (4096*1024/4 float4s per tensor) */
    dim3 cgrid(4096, 2);
    cvt_kv<<<cgrid, 256>>>(k, v);

    cudaFuncSetAttribute(bs_attn_mma,
                         cudaFuncAttributeMaxDynamicSharedMemorySize, SMEM_BYTES);
    bs_attn_mma<<<512, 256, SMEM_BYTES>>>(q, out);
}